// round 2
// baseline (speedup 1.0000x reference)
#include <cuda_runtime.h>
#include <math.h>

// Problem constants
#define BDIM 4
#define CH   128      // dim
#define C3   384      // 3*dim
#define HH   128
#define WW   128
#define HW   (HH*WW)

// Scratch (static device allocations — no cudaMalloc allowed)
__device__ float g_t1 [BDIM * C3 * HW];   // after qkv1 1x1 conv   (96 MB)
__device__ float g_qkv[BDIM * C3 * HW];   // after qkv2 3x3 conv   (96 MB)
__device__ float g_att[BDIM * CH * HW];   // after attention        (32 MB)

// ---------------------------------------------------------------------------
// Kernel 1/4: pointwise conv = GEMM  Y[b,co,h,w] = sum_ci W[co,ci] * X[b,ci,h,w]
// Cin fixed at 128. CTA = one (b,h) row (128 pixels) x 64 couts. 256 threads,
// each computes an 8(co) x 4(w) microtile. X and W staged in smem.
// ---------------------------------------------------------------------------
__global__ __launch_bounds__(256) void gemm1x1_kernel(
    const float* __restrict__ X,   // (B,128,H,W)
    const float* __restrict__ Wt,  // (M,128)
    float* __restrict__ Y,         // (B,M,H,W)
    int M)
{
    extern __shared__ float sm[];
    float* Xs = sm;                 // [128][128]  (ci, w)
    float* Ws = sm + 128 * 128;     // [128][68]   (ci, co) padded

    const int row = blockIdx.x;           // b*H + h
    const int b   = row >> 7;
    const int h   = row & 127;
    const int co0 = blockIdx.y * 64;
    const int tid = threadIdx.x;

    // Stage X row block: 128 ci x 128 w (float4, coalesced)
    {
        const float* xbase = X + ((size_t)b * CH) * HW + (size_t)h * WW;
        for (int i4 = tid; i4 < 128 * 32; i4 += 256) {
            int ci = i4 >> 5;
            int w4 = (i4 & 31) << 2;
            float4 v = *reinterpret_cast<const float4*>(xbase + (size_t)ci * HW + w4);
            *reinterpret_cast<float4*>(Xs + ci * 128 + w4) = v;
        }
    }
    // Stage W tile transposed: Ws[ci][co]
    for (int idx = tid; idx < 64 * 128; idx += 256) {
        int co = idx >> 7;
        int ci = idx & 127;
        Ws[ci * 68 + co] = Wt[(size_t)(co0 + co) * 128 + ci];
    }
    __syncthreads();

    const int tx = tid & 31;     // pixel group: w = tx*4 .. +3
    const int ty = tid >> 5;     // cout group:  co = ty*8 .. +7
    const int w0 = tx * 4;
    const int c0 = ty * 8;

    float acc[8][4];
#pragma unroll
    for (int j = 0; j < 8; j++)
#pragma unroll
        for (int m = 0; m < 4; m++) acc[j][m] = 0.f;

#pragma unroll 2
    for (int ci = 0; ci < 128; ci++) {
        float4 xv = *reinterpret_cast<const float4*>(Xs + ci * 128 + w0);
        const float* wr = Ws + ci * 68 + c0;
        float4 wa = *reinterpret_cast<const float4*>(wr);
        float4 wb = *reinterpret_cast<const float4*>(wr + 4);
        float wv[8] = {wa.x, wa.y, wa.z, wa.w, wb.x, wb.y, wb.z, wb.w};
#pragma unroll
        for (int j = 0; j < 8; j++) {
            acc[j][0] += wv[j] * xv.x;
            acc[j][1] += wv[j] * xv.y;
            acc[j][2] += wv[j] * xv.z;
            acc[j][3] += wv[j] * xv.w;
        }
    }

#pragma unroll
    for (int j = 0; j < 8; j++) {
        float4 o = make_float4(acc[j][0], acc[j][1], acc[j][2], acc[j][3]);
        *reinterpret_cast<float4*>(
            Y + (((size_t)b * M + co0 + c0 + j) * HH + h) * WW + w0) = o;
    }
}

// ---------------------------------------------------------------------------
// Kernel 2: 3x3 SAME conv 384->384 as implicit GEMM.
// CTA = one (b,h) row x 128 couts. K loop over ci chunks of 8 (x9 taps).
// 256 threads as 16x16; each thread: 8(co, contiguous) x 8(w, stride 16).
// ---------------------------------------------------------------------------
#define KC  8
#define XP  132   // padded row width for haloed input (cols 0..129 = w -1..128)

__global__ __launch_bounds__(256) void conv3x3_kernel(const float* __restrict__ Wg)
{
    extern __shared__ float sm[];
    float* Ws = sm;               // [72][128]  (k = ci*9+r*3+s, co)
    float* Xs = sm + 72 * 128;    // [KC][3][XP]

    const int row = blockIdx.x;          // b*H + h
    const int b   = row >> 7;
    const int h   = row & 127;
    const int co0 = blockIdx.y * 128;
    const int tid = threadIdx.x;
    const int tx  = tid & 15;
    const int ty  = tid >> 4;
    const int c0  = ty * 8;

    const int coL   = tid >> 1;          // 0..127
    const int halfk = (tid & 1) * 36;    // 0 or 36

    float acc[8][8];
#pragma unroll
    for (int j = 0; j < 8; j++)
#pragma unroll
        for (int i = 0; i < 8; i++) acc[j][i] = 0.f;

    for (int ci0 = 0; ci0 < C3; ci0 += KC) {
        __syncthreads();  // protect previous iteration's reads

        // Stage weights: Ws[k][co] = W2[co0+co][ci0 + k/9][ (k%9)/3 ][ k%3 ]
        {
            const float* wsrc = Wg + (size_t)(co0 + coL) * (C3 * 9) + ci0 * 9 + halfk;
            float* wdst = Ws + halfk * 128 + coL;
#pragma unroll
            for (int m = 0; m < 36; m++) wdst[m * 128] = wsrc[m];
        }
        // Stage haloed input rows with zero pad: Xs[ci][r][c], c=0..129 -> w = c-1
        for (int idx = tid; idx < KC * 3 * 130; idx += 256) {
            int c  = idx % 130;
            int t  = idx / 130;
            int r  = t % 3;
            int ci = t / 3;
            int wsrc = c - 1;
            int hsrc = h + r - 1;
            float v = 0.f;
            if ((unsigned)wsrc < 128u && (unsigned)hsrc < 128u)
                v = g_t1[(((size_t)b * C3 + ci0 + ci) * HH + hsrc) * WW + wsrc];
            Xs[(ci * 3 + r) * XP + c] = v;
        }
        __syncthreads();

#pragma unroll
        for (int ci = 0; ci < KC; ci++) {
#pragma unroll
            for (int r = 0; r < 3; r++) {
                const float* xrow = Xs + (ci * 3 + r) * XP + tx;
#pragma unroll
                for (int s = 0; s < 3; s++) {
                    const int k = ci * 9 + r * 3 + s;
                    const float* wrow = Ws + k * 128 + c0;
                    float4 wa = *reinterpret_cast<const float4*>(wrow);
                    float4 wb = *reinterpret_cast<const float4*>(wrow + 4);
                    float av[8] = {wa.x, wa.y, wa.z, wa.w, wb.x, wb.y, wb.z, wb.w};
                    float bv[8];
#pragma unroll
                    for (int i = 0; i < 8; i++) bv[i] = xrow[s + 16 * i];
#pragma unroll
                    for (int j = 0; j < 8; j++)
#pragma unroll
                        for (int i = 0; i < 8; i++)
                            acc[j][i] += av[j] * bv[i];
                }
            }
        }
    }

#pragma unroll
    for (int j = 0; j < 8; j++) {
        float* ybase = g_qkv + (((size_t)b * C3 + co0 + c0 + j) * HH + h) * WW + tx;
#pragma unroll
        for (int i = 0; i < 8; i++) ybase[16 * i] = acc[j][i];
    }
}

// ---------------------------------------------------------------------------
// Kernel 3: per-(b,c) spatial attention over width.
//  q,k L2-normalized over w (folded into score scaling), S = q k^T * scale[c],
//  softmax rows, O = S v. One CTA per (b,c) slice; k^T and v in smem.
// ---------------------------------------------------------------------------
__global__ __launch_bounds__(256) void attn_kernel(const float* __restrict__ scale)
{
    extern __shared__ float sm[];
    float* kT   = sm;                    // [128][132] : kT[w*132 + g]
    float* Vs   = sm + 128 * 132;        // [128][132] : Vs[g*132 + w]
    float* qbuf = Vs + 128 * 132;        // [8][132]  per-warp q row
    float* kinv = qbuf + 8 * 132;        // [128]

    const int bc   = blockIdx.x;
    const int b    = bc >> 7;
    const int c    = bc & 127;
    const int tid  = threadIdx.x;
    const int lane = tid & 31;
    const int wp   = tid >> 5;
    const unsigned FULL = 0xffffffffu;

    const float* qg = g_qkv + ((size_t)b * C3 + c) * HW;
    const float* kg = g_qkv + ((size_t)b * C3 + CH + c) * HW;
    const float* vg = g_qkv + ((size_t)b * C3 + 2 * CH + c) * HW;

    for (int idx = tid; idx < HW; idx += 256) {
        int g = idx >> 7;
        int w = idx & 127;
        kT[w * 132 + g] = kg[idx];
        Vs[g * 132 + w] = vg[idx];
    }
    __syncthreads();

    if (tid < 128) {
        float ss = 0.f;
#pragma unroll 4
        for (int w = 0; w < 128; w++) {
            float kv = kT[w * 132 + tid];
            ss += kv * kv;
        }
        kinv[tid] = 1.0f / fmaxf(sqrtf(ss), 1e-12f);
    }
    __syncthreads();

    const float sc = scale[c];
    const int g0 = lane * 4;

    for (int i = wp; i < 128; i += 8) {
        // load + normalize q row i
        float4 q4 = *reinterpret_cast<const float4*>(qg + (size_t)i * WW + lane * 4);
        float ss = q4.x * q4.x + q4.y * q4.y + q4.z * q4.z + q4.w * q4.w;
#pragma unroll
        for (int off = 16; off; off >>= 1) ss += __shfl_xor_sync(FULL, ss, off);
        float qf = sc / fmaxf(sqrtf(ss), 1e-12f);

        *reinterpret_cast<float4*>(qbuf + wp * 132 + lane * 4) = q4;
        __syncwarp();

        // scores: lane owns g = lane*4 .. +3
        float s0 = 0.f, s1 = 0.f, s2 = 0.f, s3 = 0.f;
        const float* kcol = kT + g0;
        const float* qrow = qbuf + wp * 132;
#pragma unroll 4
        for (int w = 0; w < 128; w++) {
            float  qv = qrow[w];
            float4 kv = *reinterpret_cast<const float4*>(kcol + w * 132);
            s0 += qv * kv.x; s1 += qv * kv.y; s2 += qv * kv.z; s3 += qv * kv.w;
        }
        s0 *= qf * kinv[g0 + 0];
        s1 *= qf * kinv[g0 + 1];
        s2 *= qf * kinv[g0 + 2];
        s3 *= qf * kinv[g0 + 3];

        // softmax over 128 values spread across warp
        float mx = fmaxf(fmaxf(s0, s1), fmaxf(s2, s3));
#pragma unroll
        for (int off = 16; off; off >>= 1) mx = fmaxf(mx, __shfl_xor_sync(FULL, mx, off));
        float pr[4];
        pr[0] = __expf(s0 - mx); pr[1] = __expf(s1 - mx);
        pr[2] = __expf(s2 - mx); pr[3] = __expf(s3 - mx);
        float psum = pr[0] + pr[1] + pr[2] + pr[3];
#pragma unroll
        for (int off = 16; off; off >>= 1) psum += __shfl_xor_sync(FULL, psum, off);
        float inv = 1.0f / psum;

        // O row: lane owns w = lane*4 .. +3
        float o0 = 0.f, o1 = 0.f, o2 = 0.f, o3 = 0.f;
#pragma unroll
        for (int jj = 0; jj < 4; jj++) {
#pragma unroll
            for (int l = 0; l < 32; l++) {
                float pv = __shfl_sync(FULL, pr[jj], l);
                int g = l * 4 + jj;
                float4 vv = *reinterpret_cast<const float4*>(Vs + g * 132 + lane * 4);
                o0 += pv * vv.x; o1 += pv * vv.y; o2 += pv * vv.z; o3 += pv * vv.w;
            }
        }
        float4 orow = make_float4(o0 * inv, o1 * inv, o2 * inv, o3 * inv);
        *reinterpret_cast<float4*>(
            g_att + (((size_t)b * CH + c) * HH + i) * WW + lane * 4) = orow;
        __syncwarp();
    }
}

// ---------------------------------------------------------------------------
// Launch
// ---------------------------------------------------------------------------
extern "C" void kernel_launch(void* const* d_in, const int* in_sizes, int n_in,
                              void* d_out, int out_size)
{
    (void)in_sizes; (void)n_in; (void)out_size;
    const float* x     = (const float*)d_in[0];
    const float* w1    = (const float*)d_in[1];  // (384,128,1,1)
    const float* w2    = (const float*)d_in[2];  // (384,384,3,3)
    const float* wproj = (const float*)d_in[3];  // (128,128,1,1)
    const float* scale = (const float*)d_in[4];  // (128,1,1)
    float* out = (float*)d_out;

    void *p_t1 = nullptr, *p_att = nullptr;
    cudaGetSymbolAddress(&p_t1, g_t1);
    cudaGetSymbolAddress(&p_att, g_att);

    const int SMEM_GEMM = (128 * 128 + 128 * 68) * 4;             // 100,352 B
    const int SMEM_CONV = (72 * 128 + KC * 3 * XP) * 4;           //  49,536 B
    const int SMEM_ATTN = (128 * 132 * 2 + 8 * 132 + 128) * 4;    // 139,904 B

    cudaFuncSetAttribute(gemm1x1_kernel, cudaFuncAttributeMaxDynamicSharedMemorySize, SMEM_GEMM);
    cudaFuncSetAttribute(conv3x3_kernel, cudaFuncAttributeMaxDynamicSharedMemorySize, SMEM_CONV);
    cudaFuncSetAttribute(attn_kernel,    cudaFuncAttributeMaxDynamicSharedMemorySize, SMEM_ATTN);

    // 1) qkv 1x1: x(128ch) -> g_t1(384ch)
    gemm1x1_kernel<<<dim3(BDIM * HH, C3 / 64), 256, SMEM_GEMM>>>(
        x, w1, (float*)p_t1, C3);

    // 2) qkv 3x3: g_t1 -> g_qkv
    conv3x3_kernel<<<dim3(BDIM * HH, C3 / 128), 256, SMEM_CONV>>>(w2);

    // 3) attention: g_qkv -> g_att
    attn_kernel<<<BDIM * CH, 256, SMEM_ATTN>>>(scale);

    // 4) proj 1x1: g_att(128ch) -> out(128ch)
    gemm1x1_kernel<<<dim3(BDIM * HH, CH / 64), 256, SMEM_GEMM>>>(
        (const float*)p_att, wproj, out, CH);
}

// round 4
// speedup vs baseline: 3.0918x; 3.0918x over previous
#include <cuda_runtime.h>
#include <cuda_bf16.h>
#include <cstdint>
#include <math.h>

#define BDIM 4
#define CH   128
#define C3   384
#define HH   128
#define WW   128
#define HW   (HH*WW)

__device__ __nv_bfloat16 g_xh[(size_t)BDIM * HH * WW * C3];   // qkv1 out NHWC hi
__device__ __nv_bfloat16 g_xl[(size_t)BDIM * HH * WW * C3];   // lo
__device__ __nv_bfloat16 g_wph[3 * 384 * 1152];               // W2 [r][co][s*384+ci] hi
__device__ __nv_bfloat16 g_wpl[3 * 384 * 1152];               // lo
__device__ float g_qkv[(size_t)BDIM * C3 * HW];
__device__ float g_att[(size_t)BDIM * CH * HW];

__device__ __forceinline__ uint32_t smem_to_u32(const void* p) {
    uint32_t a;
    asm("{ .reg .u64 t; cvta.to.shared.u64 t, %1; cvt.u32.u64 %0, t; }" : "=r"(a) : "l"(p));
    return a;
}
#define CP_ASYNC16(dst, src, sz) \
    asm volatile("cp.async.cg.shared.global [%0], [%1], 16, %2;" \
        :: "r"(dst), "l"(src), "r"(sz) : "memory")
#define CP_COMMIT() asm volatile("cp.async.commit_group;" ::: "memory")
#define CP_WAIT(n)  asm volatile("cp.async.wait_group %0;" :: "n"(n) : "memory")

#define LDSM_X4(r0, r1, r2, r3, addr) \
    asm volatile("ldmatrix.sync.aligned.m8n8.x4.shared.b16 {%0,%1,%2,%3}, [%4];" \
        : "=r"(r0), "=r"(r1), "=r"(r2), "=r"(r3) : "r"(addr))

#define MMA16816(c, a, b0v, b1v) \
    asm volatile("mma.sync.aligned.m16n8k16.row.col.f32.bf16.bf16.f32 " \
        "{%0,%1,%2,%3}, {%4,%5,%6,%7}, {%8,%9}, {%0,%1,%2,%3};" \
        : "+f"((c)[0]), "+f"((c)[1]), "+f"((c)[2]), "+f"((c)[3]) \
        : "r"((a)[0]), "r"((a)[1]), "r"((a)[2]), "r"((a)[3]), "r"(b0v), "r"(b1v))

// ---------------- weight prep: (co,ci,r,s) fp32 -> [r][co][s*384+ci] bf16 hi/lo
__global__ void wprep_kernel(const float* __restrict__ w2)
{
    int idx = blockIdx.x * 256 + threadIdx.x;
    if (idx >= 384 * 384 * 9) return;
    int s = idx % 3, r = (idx / 3) % 3, ci = (idx / 9) % 384, co = idx / (9 * 384);
    float v = w2[idx];
    __nv_bfloat16 hv = __float2bfloat16(v);
    int dst = (r * 384 + co) * 1152 + s * 384 + ci;
    g_wph[dst] = hv;
    g_wpl[dst] = __float2bfloat16(v - __bfloat162float(hv));
}

// ---------------- qkv 1x1: x(NCHW) -> NHWC bf16 hi/lo ----------------
__global__ __launch_bounds__(256) void gemm1x1_qkv(
    const float* __restrict__ X, const float* __restrict__ Wt)
{
    extern __shared__ float smf[];
    float* Xs = smf;                 // [128][128]
    float* Ws = smf + 128 * 128;     // [128][68]
    const int row = blockIdx.x, b = row >> 7, hrow = row & 127;
    const int co0 = blockIdx.y * 64, tid = threadIdx.x;
    {
        const float* xb = X + ((size_t)b * CH) * HW + (size_t)hrow * WW;
        for (int i4 = tid; i4 < 128 * 32; i4 += 256) {
            int ci = i4 >> 5, w4 = (i4 & 31) << 2;
            *reinterpret_cast<float4*>(Xs + ci * 128 + w4) =
                *reinterpret_cast<const float4*>(xb + (size_t)ci * HW + w4);
        }
    }
    for (int idx = tid; idx < 64 * 128; idx += 256) {
        int co = idx >> 7, ci = idx & 127;
        Ws[ci * 68 + co] = Wt[(size_t)(co0 + co) * 128 + ci];
    }
    __syncthreads();
    const int tx = tid & 31, ty = tid >> 5, w0 = tx * 4, c0 = ty * 8;
    float acc[8][4];
#pragma unroll
    for (int j = 0; j < 8; j++)
#pragma unroll
        for (int m = 0; m < 4; m++) acc[j][m] = 0.f;
#pragma unroll 2
    for (int ci = 0; ci < 128; ci++) {
        float4 xv = *reinterpret_cast<const float4*>(Xs + ci * 128 + w0);
        const float* wr = Ws + ci * 68 + c0;
        float4 wa = *reinterpret_cast<const float4*>(wr);
        float4 wb = *reinterpret_cast<const float4*>(wr + 4);
        float wv[8] = {wa.x, wa.y, wa.z, wa.w, wb.x, wb.y, wb.z, wb.w};
#pragma unroll
        for (int j = 0; j < 8; j++) {
            acc[j][0] += wv[j] * xv.x; acc[j][1] += wv[j] * xv.y;
            acc[j][2] += wv[j] * xv.z; acc[j][3] += wv[j] * xv.w;
        }
    }
#pragma unroll
    for (int m = 0; m < 4; m++) {
        __nv_bfloat16 hb[8], lb[8];
#pragma unroll
        for (int j = 0; j < 8; j++) {
            float v = acc[j][m];
            __nv_bfloat16 hv = __float2bfloat16(v);
            hb[j] = hv;
            lb[j] = __float2bfloat16(v - __bfloat162float(hv));
        }
        size_t base = ((size_t)(b * 128 + hrow) * 128 + (w0 + m)) * 384 + co0 + c0;
        *reinterpret_cast<uint4*>(g_xh + base) = *reinterpret_cast<uint4*>(hb);
        *reinterpret_cast<uint4*>(g_xl + base) = *reinterpret_cast<uint4*>(lb);
    }
}

// ---------------- conv3x3 via mma.sync bf16 hi/lo 3-pass ----------------
// CTA: 128 couts x 128 pixels (one image row). 8 warps = 2(m) x 4(n), warp 64x32.
// K: 3 r-taps x 36 chunks of 32. Smem row (per co / per pixel) = 128B: [hi32|lo32]
// bf16, SW128 swizzled; ldmatrix non-trans matches row.col fragments (K-major).
#define NCHUNK 108
__global__ __launch_bounds__(256, 2) void conv3x3_mma()
{
    extern __shared__ __align__(1024) char smem[];
    const uint32_t sb = smem_to_u32(smem);
    const int tid = threadIdx.x, wid = tid >> 5, lane = tid & 31;
    const int bx = blockIdx.x, b = bx >> 7, h = bx & 127;
    const int co0 = blockIdx.y * 128;
    const int wm = wid & 1, wn = wid >> 1;      // warp tile: m=wm*64, n=wn*32
    const int mwbase = wm * 64, nwbase = wn * 32;

    float acc[4][4][4];
#pragma unroll
    for (int i = 0; i < 4; i++)
#pragma unroll
        for (int j = 0; j < 4; j++)
#pragma unroll
            for (int k = 0; k < 4; k++) acc[i][j][k] = 0.f;

    // stage one chunk (A:128x8 units, B:128x8 units of 16B) into buffer `buf`
    auto stage = [&](int it, int buf) {
        const int r = it / 36, kc = it % 36;
        const uint32_t abase = sb + (uint32_t)buf * 32768u;
        const uint32_t bbase = abase + 16384u;
#pragma unroll
        for (int j = 0; j < 8; j++) {
            int idx = tid + j * 256;            // 0..2047
            int rw  = (idx >> 3) & 127;         // row within A or B tile
            int u   = idx & 7;                  // 16B unit (0-3 hi, 4-7 lo)
            int kun = u & 3;
            uint32_t dof = (uint32_t)(rw * 128 + (((u ^ (rw & 7))) << 4));
            if (idx < 1024) {
                const __nv_bfloat16* src = ((u >> 2) ? g_wpl : g_wph)
                    + ((size_t)(r * 384 + co0 + rw) * 1152 + kc * 32 + kun * 8);
                CP_ASYNC16(abase + dof, src, 16);
            } else {
                int hr = h + r - 1;
                int L  = (rw - 1) * 384 + kc * 32 + kun * 8;
                bool ok = ((unsigned)hr < 128u) && ((unsigned)L < 49152u);
                const __nv_bfloat16* src = ((u >> 2) ? g_xl : g_xh)
                    + (ok ? ((size_t)(b * 128 + hr) * 49152 + L) : 0);
                CP_ASYNC16(bbase + dof, src, ok ? 16 : 0);
            }
        }
        CP_COMMIT();
    };

    stage(0, 0);
    for (int it = 0; it < NCHUNK; it++) {
        const int buf = it & 1;
        if (it + 1 < NCHUNK) { stage(it + 1, buf ^ 1); CP_WAIT(1); }
        else                 { CP_WAIT(0); }
        __syncthreads();

        const uint32_t abase = sb + (uint32_t)buf * 32768u;
        const uint32_t bbase = abase + 16384u;
#pragma unroll
        for (int ks = 0; ks < 2; ks++) {        // two k16 steps per chunk
            const int kg0 = ks * 2;
            uint32_t ah[4][4], bh[2][4], bl[2][4], al[4][4];
            const int q   = lane >> 3;          // quad 0..3
            const int qr  = (q & 1) * 8 + (lane & 7);
            const int qk  = q >> 1;             // 0,0,1,1
            // A hi fragments (m64)
#pragma unroll
            for (int mf = 0; mf < 4; mf++) {
                int rw = mwbase + mf * 16 + qr;
                int u  = kg0 + qk;
                uint32_t ad = abase + (uint32_t)(rw * 128 + ((u ^ (rw & 7)) << 4));
                LDSM_X4(ah[mf][0], ah[mf][1], ah[mf][2], ah[mf][3], ad);
            }
            // B hi fragments (n32 = 2 x n16)
#pragma unroll
            for (int g = 0; g < 2; g++) {
                int rw = nwbase + g * 16 + qr;
                int u  = kg0 + qk;
                uint32_t ad = bbase + (uint32_t)(rw * 128 + ((u ^ (rw & 7)) << 4));
                LDSM_X4(bh[g][0], bh[g][1], bh[g][2], bh[g][3], ad);
            }
            // pass 1: Ah * Bh
#pragma unroll
            for (int mf = 0; mf < 4; mf++)
#pragma unroll
                for (int nf = 0; nf < 4; nf++)
                    MMA16816(acc[mf][nf], ah[mf],
                             bh[nf >> 1][nf & 1], bh[nf >> 1][(nf & 1) + 2]);
            // B lo
#pragma unroll
            for (int g = 0; g < 2; g++) {
                int rw = nwbase + g * 16 + qr;
                int u  = 4 + kg0 + qk;
                uint32_t ad = bbase + (uint32_t)(rw * 128 + ((u ^ (rw & 7)) << 4));
                LDSM_X4(bl[g][0], bl[g][1], bl[g][2], bl[g][3], ad);
            }
            // pass 2: Ah * Bl
#pragma unroll
            for (int mf = 0; mf < 4; mf++)
#pragma unroll
                for (int nf = 0; nf < 4; nf++)
                    MMA16816(acc[mf][nf], ah[mf],
                             bl[nf >> 1][nf & 1], bl[nf >> 1][(nf & 1) + 2]);
            // A lo
#pragma unroll
            for (int mf = 0; mf < 4; mf++) {
                int rw = mwbase + mf * 16 + qr;
                int u  = 4 + kg0 + qk;
                uint32_t ad = abase + (uint32_t)(rw * 128 + ((u ^ (rw & 7)) << 4));
                LDSM_X4(al[mf][0], al[mf][1], al[mf][2], al[mf][3], ad);
            }
            // pass 3: Al * Bh
#pragma unroll
            for (int mf = 0; mf < 4; mf++)
#pragma unroll
                for (int nf = 0; nf < 4; nf++)
                    MMA16816(acc[mf][nf], al[mf],
                             bh[nf >> 1][nf & 1], bh[nf >> 1][(nf & 1) + 2]);
        }
        __syncthreads();
    }

    // epilogue: regs -> g_qkv (NCHW fp32)
    const int gid = lane >> 2, tg = lane & 3;
#pragma unroll
    for (int mf = 0; mf < 4; mf++) {
        int co = co0 + mwbase + mf * 16 + gid;
        float* base0 = g_qkv + (((size_t)b * C3 + co) * HH + h) * WW;
        float* base1 = g_qkv + (((size_t)b * C3 + co + 8) * HH + h) * WW;
#pragma unroll
        for (int nf = 0; nf < 4; nf++) {
            int w = nwbase + nf * 8 + tg * 2;
            *reinterpret_cast<float2*>(base0 + w) = make_float2(acc[mf][nf][0], acc[mf][nf][1]);
            *reinterpret_cast<float2*>(base1 + w) = make_float2(acc[mf][nf][2], acc[mf][nf][3]);
        }
    }
}

// ---------------- proj 1x1 fp32 (NCHW) ----------------
__global__ __launch_bounds__(256) void gemm1x1_kernel(
    const float* __restrict__ X, const float* __restrict__ Wt,
    float* __restrict__ Y, int M)
{
    extern __shared__ float smf[];
    float* Xs = smf;
    float* Ws = smf + 128 * 128;
    const int row = blockIdx.x, b = row >> 7, hrow = row & 127;
    const int co0 = blockIdx.y * 64, tid = threadIdx.x;
    {
        const float* xb = X + ((size_t)b * CH) * HW + (size_t)hrow * WW;
        for (int i4 = tid; i4 < 128 * 32; i4 += 256) {
            int ci = i4 >> 5, w4 = (i4 & 31) << 2;
            *reinterpret_cast<float4*>(Xs + ci * 128 + w4) =
                *reinterpret_cast<const float4*>(xb + (size_t)ci * HW + w4);
        }
    }
    for (int idx = tid; idx < 64 * 128; idx += 256) {
        int co = idx >> 7, ci = idx & 127;
        Ws[ci * 68 + co] = Wt[(size_t)(co0 + co) * 128 + ci];
    }
    __syncthreads();
    const int tx = tid & 31, ty = tid >> 5, w0 = tx * 4, c0 = ty * 8;
    float acc[8][4];
#pragma unroll
    for (int j = 0; j < 8; j++)
#pragma unroll
        for (int m = 0; m < 4; m++) acc[j][m] = 0.f;
#pragma unroll 2
    for (int ci = 0; ci < 128; ci++) {
        float4 xv = *reinterpret_cast<const float4*>(Xs + ci * 128 + w0);
        const float* wr = Ws + ci * 68 + c0;
        float4 wa = *reinterpret_cast<const float4*>(wr);
        float4 wb = *reinterpret_cast<const float4*>(wr + 4);
        float wv[8] = {wa.x, wa.y, wa.z, wa.w, wb.x, wb.y, wb.z, wb.w};
#pragma unroll
        for (int j = 0; j < 8; j++) {
            acc[j][0] += wv[j] * xv.x; acc[j][1] += wv[j] * xv.y;
            acc[j][2] += wv[j] * xv.z; acc[j][3] += wv[j] * xv.w;
        }
    }
#pragma unroll
    for (int j = 0; j < 8; j++) {
        float4 o = make_float4(acc[j][0], acc[j][1], acc[j][2], acc[j][3]);
        *reinterpret_cast<float4*>(
            Y + (((size_t)b * M + co0 + c0 + j) * HH + hrow) * WW + w0) = o;
    }
}

// ---------------- per-(b,c) attention over width ----------------
__global__ __launch_bounds__(256) void attn_kernel(const float* __restrict__ scale)
{
    extern __shared__ float smf[];
    float* kT   = smf;                   // [128][132]
    float* Vs   = smf + 128 * 132;       // [128][132]
    float* qbuf = Vs + 128 * 132;        // [8][132]
    float* kinv = qbuf + 8 * 132;        // [128]
    const int bc = blockIdx.x, b = bc >> 7, c = bc & 127;
    const int tid = threadIdx.x, lane = tid & 31, wp = tid >> 5;
    const unsigned FULL = 0xffffffffu;
    const float* qg = g_qkv + ((size_t)b * C3 + c) * HW;
    const float* kg = g_qkv + ((size_t)b * C3 + CH + c) * HW;
    const float* vg = g_qkv + ((size_t)b * C3 + 2 * CH + c) * HW;

    for (int idx = tid; idx < HW; idx += 256) {
        int g = idx >> 7, w = idx & 127;
        kT[w * 132 + g] = kg[idx];
        Vs[g * 132 + w] = vg[idx];
    }
    __syncthreads();
    if (tid < 128) {
        float ss = 0.f;
#pragma unroll 4
        for (int w = 0; w < 128; w++) { float kv = kT[w * 132 + tid]; ss += kv * kv; }
        kinv[tid] = 1.0f / fmaxf(sqrtf(ss), 1e-12f);
    }
    __syncthreads();
    const float sc = scale[c];
    const int g0 = lane * 4;
    for (int i = wp; i < 128; i += 8) {
        float4 q4 = *reinterpret_cast<const float4*>(qg + (size_t)i * WW + lane * 4);
        float ss = q4.x * q4.x + q4.y * q4.y + q4.z * q4.z + q4.w * q4.w;
#pragma unroll
        for (int off = 16; off; off >>= 1) ss += __shfl_xor_sync(FULL, ss, off);
        float qf = sc / fmaxf(sqrtf(ss), 1e-12f);
        *reinterpret_cast<float4*>(qbuf + wp * 132 + lane * 4) = q4;
        __syncwarp();
        float s0 = 0.f, s1 = 0.f, s2 = 0.f, s3 = 0.f;
        const float* kcol = kT + g0;
        const float* qrow = qbuf + wp * 132;
#pragma unroll 4
        for (int w = 0; w < 128; w++) {
            float qv = qrow[w];
            float4 kv = *reinterpret_cast<const float4*>(kcol + w * 132);
            s0 += qv * kv.x; s1 += qv * kv.y; s2 += qv * kv.z; s3 += qv * kv.w;
        }
        s0 *= qf * kinv[g0 + 0]; s1 *= qf * kinv[g0 + 1];
        s2 *= qf * kinv[g0 + 2]; s3 *= qf * kinv[g0 + 3];
        float mx = fmaxf(fmaxf(s0, s1), fmaxf(s2, s3));
#pragma unroll
        for (int off = 16; off; off >>= 1) mx = fmaxf(mx, __shfl_xor_sync(FULL, mx, off));
        float pr[4];
        pr[0] = __expf(s0 - mx); pr[1] = __expf(s1 - mx);
        pr[2] = __expf(s2 - mx); pr[3] = __expf(s3 - mx);
        float psum = pr[0] + pr[1] + pr[2] + pr[3];
#pragma unroll
        for (int off = 16; off; off >>= 1) psum += __shfl_xor_sync(FULL, psum, off);
        float inv = 1.0f / psum;
        float o0 = 0.f, o1 = 0.f, o2 = 0.f, o3 = 0.f;
#pragma unroll
        for (int jj = 0; jj < 4; jj++) {
#pragma unroll
            for (int l = 0; l < 32; l++) {
                float pv = __shfl_sync(FULL, pr[jj], l);
                int g = l * 4 + jj;
                float4 vv = *reinterpret_cast<const float4*>(Vs + g * 132 + lane * 4);
                o0 += pv * vv.x; o1 += pv * vv.y; o2 += pv * vv.z; o3 += pv * vv.w;
            }
        }
        float4 orow = make_float4(o0 * inv, o1 * inv, o2 * inv, o3 * inv);
        *reinterpret_cast<float4*>(
            g_att + (((size_t)b * CH + c) * HH + i) * WW + lane * 4) = orow;
        __syncwarp();
    }
}

// ---------------- launch ----------------
extern "C" void kernel_launch(void* const* d_in, const int* in_sizes, int n_in,
                              void* d_out, int out_size)
{
    (void)in_sizes; (void)n_in; (void)out_size;
    const float* x     = (const float*)d_in[0];
    const float* w1    = (const float*)d_in[1];
    const float* w2    = (const float*)d_in[2];
    const float* wproj = (const float*)d_in[3];
    const float* scale = (const float*)d_in[4];
    float* out = (float*)d_out;

    void* p_att = nullptr;
    cudaGetSymbolAddress(&p_att, g_att);

    const int SMEM_GEMM = (128 * 128 + 128 * 68) * 4;
    const int SMEM_CONV = 2 * 32768;                               // 64 KB
    const int SMEM_ATTN = (128 * 132 * 2 + 8 * 132 + 128) * 4;

    cudaFuncSetAttribute(gemm1x1_qkv,    cudaFuncAttributeMaxDynamicSharedMemorySize, SMEM_GEMM);
    cudaFuncSetAttribute(gemm1x1_kernel, cudaFuncAttributeMaxDynamicSharedMemorySize, SMEM_GEMM);
    cudaFuncSetAttribute(conv3x3_mma,    cudaFuncAttributeMaxDynamicSharedMemorySize, SMEM_CONV);
    cudaFuncSetAttribute(attn_kernel,    cudaFuncAttributeMaxDynamicSharedMemorySize, SMEM_ATTN);

    wprep_kernel<<<(384 * 384 * 9 + 255) / 256, 256>>>(w2);
    gemm1x1_qkv<<<dim3(BDIM * HH, C3 / 64), 256, SMEM_GEMM>>>(x, w1);
    conv3x3_mma<<<dim3(BDIM * HH, C3 / 128), 256, SMEM_CONV>>>();
    attn_kernel<<<BDIM * CH, 256, SMEM_ATTN>>>(scale);
    gemm1x1_kernel<<<dim3(BDIM * HH, CH / 64), 256, SMEM_GEMM>>>(
        (const float*)p_att, wproj, out, CH);
}

// round 5
// speedup vs baseline: 7.8990x; 2.5548x over previous
#include <cuda_runtime.h>
#include <cuda_fp16.h>
#include <cstdint>
#include <math.h>

#define BDIM 4
#define CH   128
#define C3   384
#define HH   128
#define WW   128
#define HW   (HH*WW)

__device__ __half g_x [(size_t)BDIM * HH * WW * C3];   // qkv1 out NHWC fp16
__device__ __half g_wp[3 * 384 * 1152];                // W2 [r][co][s*384+ci] fp16
__device__ float g_qkv[(size_t)BDIM * C3 * HW];        // conv3x3 out NCHW fp32
__device__ float g_att[(size_t)BDIM * CH * HW];

__device__ __forceinline__ uint32_t smem_to_u32(const void* p) {
    uint32_t a;
    asm("{ .reg .u64 t; cvta.to.shared.u64 t, %1; cvt.u32.u64 %0, t; }" : "=r"(a) : "l"(p));
    return a;
}
#define CP_ASYNC16(dst, src, sz) \
    asm volatile("cp.async.cg.shared.global [%0], [%1], 16, %2;" \
        :: "r"(dst), "l"(src), "r"(sz) : "memory")
#define CP_COMMIT() asm volatile("cp.async.commit_group;" ::: "memory")
#define CP_WAIT(n)  asm volatile("cp.async.wait_group %0;" :: "n"(n) : "memory")

#define LDSM_X4(r0, r1, r2, r3, addr) \
    asm volatile("ldmatrix.sync.aligned.m8n8.x4.shared.b16 {%0,%1,%2,%3}, [%4];" \
        : "=r"(r0), "=r"(r1), "=r"(r2), "=r"(r3) : "r"(addr))
#define LDSM_X4_T(r0, r1, r2, r3, addr) \
    asm volatile("ldmatrix.sync.aligned.m8n8.x4.trans.shared.b16 {%0,%1,%2,%3}, [%4];" \
        : "=r"(r0), "=r"(r1), "=r"(r2), "=r"(r3) : "r"(addr))

#define MMA16816(c, a, b0v, b1v) \
    asm volatile("mma.sync.aligned.m16n8k16.row.col.f32.f16.f16.f32 " \
        "{%0,%1,%2,%3}, {%4,%5,%6,%7}, {%8,%9}, {%0,%1,%2,%3};" \
        : "+f"((c)[0]), "+f"((c)[1]), "+f"((c)[2]), "+f"((c)[3]) \
        : "r"((a)[0]), "r"((a)[1]), "r"((a)[2]), "r"((a)[3]), "r"(b0v), "r"(b1v))

// ---------------- weight prep: (co,ci,r,s) fp32 -> [r][co][s*384+ci] fp16
__global__ void wprep_kernel(const float* __restrict__ w2)
{
    int idx = blockIdx.x * 256 + threadIdx.x;
    if (idx >= 384 * 384 * 9) return;
    int s = idx % 3, r = (idx / 3) % 3, ci = (idx / 9) % 384, co = idx / (9 * 384);
    g_wp[(r * 384 + co) * 1152 + s * 384 + ci] = __float2half(w2[idx]);
}

// ---------------- qkv 1x1: x(NCHW fp32) -> NHWC fp16 ----------------
__global__ __launch_bounds__(256) void gemm1x1_qkv(
    const float* __restrict__ X, const float* __restrict__ Wt)
{
    extern __shared__ float smf[];
    float* Xs = smf;                 // [128][128]
    float* Ws = smf + 128 * 128;     // [128][68]
    const int row = blockIdx.x, b = row >> 7, hrow = row & 127;
    const int co0 = blockIdx.y * 64, tid = threadIdx.x;
    {
        const float* xb = X + ((size_t)b * CH) * HW + (size_t)hrow * WW;
        for (int i4 = tid; i4 < 128 * 32; i4 += 256) {
            int ci = i4 >> 5, w4 = (i4 & 31) << 2;
            *reinterpret_cast<float4*>(Xs + ci * 128 + w4) =
                *reinterpret_cast<const float4*>(xb + (size_t)ci * HW + w4);
        }
    }
    for (int idx = tid; idx < 64 * 128; idx += 256) {
        int co = idx >> 7, ci = idx & 127;
        Ws[ci * 68 + co] = Wt[(size_t)(co0 + co) * 128 + ci];
    }
    __syncthreads();
    const int tx = tid & 31, ty = tid >> 5, w0 = tx * 4, c0 = ty * 8;
    float acc[8][4];
#pragma unroll
    for (int j = 0; j < 8; j++)
#pragma unroll
        for (int m = 0; m < 4; m++) acc[j][m] = 0.f;
#pragma unroll 2
    for (int ci = 0; ci < 128; ci++) {
        float4 xv = *reinterpret_cast<const float4*>(Xs + ci * 128 + w0);
        const float* wr = Ws + ci * 68 + c0;
        float4 wa = *reinterpret_cast<const float4*>(wr);
        float4 wb = *reinterpret_cast<const float4*>(wr + 4);
        float wv[8] = {wa.x, wa.y, wa.z, wa.w, wb.x, wb.y, wb.z, wb.w};
#pragma unroll
        for (int j = 0; j < 8; j++) {
            acc[j][0] += wv[j] * xv.x; acc[j][1] += wv[j] * xv.y;
            acc[j][2] += wv[j] * xv.z; acc[j][3] += wv[j] * xv.w;
        }
    }
#pragma unroll
    for (int m = 0; m < 4; m++) {
        __half hb[8];
#pragma unroll
        for (int j = 0; j < 8; j++) hb[j] = __float2half(acc[j][m]);
        size_t base = ((size_t)(b * 128 + hrow) * 128 + (w0 + m)) * 384 + co0 + c0;
        *reinterpret_cast<uint4*>(g_x + base) = *reinterpret_cast<uint4*>(hb);
    }
}

// ---------------- conv3x3 via mma.sync fp16 single pass ----------------
// CTA: 128 couts x 128 pixels (one image row). 8 warps = 2(m) x 4(n), warp 64x32.
// K: 3 r-taps x 18 chunks of 64. Smem row = 128B = 64 fp16, swizzled.
#define NCHUNK 54
__global__ __launch_bounds__(256, 2) void conv3x3_mma()
{
    extern __shared__ __align__(1024) char smem[];
    const uint32_t sb = smem_to_u32(smem);
    const int tid = threadIdx.x, wid = tid >> 5, lane = tid & 31;
    const int bx = blockIdx.x, b = bx >> 7, h = bx & 127;
    const int co0 = blockIdx.y * 128;
    const int wm = wid & 1, wn = wid >> 1;
    const int mwbase = wm * 64, nwbase = wn * 32;

    float acc[4][4][4];
#pragma unroll
    for (int i = 0; i < 4; i++)
#pragma unroll
        for (int j = 0; j < 4; j++)
#pragma unroll
            for (int k = 0; k < 4; k++) acc[i][j][k] = 0.f;

    auto stage = [&](int it, int buf) {
        const int r = it / 18, kc = it % 18;
        const uint32_t abase = sb + (uint32_t)buf * 32768u;
        const uint32_t bbase = abase + 16384u;
#pragma unroll
        for (int j = 0; j < 8; j++) {
            int idx = tid + j * 256;            // 0..2047
            int rw  = (idx >> 3) & 127;
            int u   = idx & 7;
            uint32_t dof = (uint32_t)(rw * 128 + ((u ^ (rw & 7)) << 4));
            if (idx < 1024) {
                const __half* src = g_wp +
                    ((size_t)(r * 384 + co0 + rw) * 1152 + kc * 64 + u * 8);
                CP_ASYNC16(abase + dof, src, 16);
            } else {
                int hr = h + r - 1;
                int L  = (rw - 1) * 384 + kc * 64 + u * 8;
                bool ok = ((unsigned)hr < 128u) && ((unsigned)L < 49152u);
                const __half* src = g_x +
                    (ok ? ((size_t)(b * 128 + hr) * 49152 + L) : 0);
                CP_ASYNC16(bbase + dof, src, ok ? 16 : 0);
            }
        }
        CP_COMMIT();
    };

    stage(0, 0);
    for (int it = 0; it < NCHUNK; it++) {
        const int buf = it & 1;
        if (it + 1 < NCHUNK) { stage(it + 1, buf ^ 1); CP_WAIT(1); }
        else                 { CP_WAIT(0); }
        __syncthreads();

        const uint32_t abase = sb + (uint32_t)buf * 32768u;
        const uint32_t bbase = abase + 16384u;
        const int q4 = lane >> 3;
        const int qr = (q4 & 1) * 8 + (lane & 7);
        const int qk = q4 >> 1;
#pragma unroll
        for (int ks = 0; ks < 4; ks++) {
            const int u = ks * 2 + qk;
            uint32_t ah[4][4], bh[2][4];
#pragma unroll
            for (int mf = 0; mf < 4; mf++) {
                int rw = mwbase + mf * 16 + qr;
                LDSM_X4(ah[mf][0], ah[mf][1], ah[mf][2], ah[mf][3],
                        abase + (uint32_t)(rw * 128 + ((u ^ (rw & 7)) << 4)));
            }
#pragma unroll
            for (int g = 0; g < 2; g++) {
                int rw = nwbase + g * 16 + qr;
                LDSM_X4(bh[g][0], bh[g][1], bh[g][2], bh[g][3],
                        bbase + (uint32_t)(rw * 128 + ((u ^ (rw & 7)) << 4)));
            }
#pragma unroll
            for (int mf = 0; mf < 4; mf++)
#pragma unroll
                for (int nf = 0; nf < 4; nf++)
                    MMA16816(acc[mf][nf], ah[mf],
                             bh[nf >> 1][nf & 1], bh[nf >> 1][(nf & 1) + 2]);
        }
        __syncthreads();
    }

    const int gid = lane >> 2, tg = lane & 3;
#pragma unroll
    for (int mf = 0; mf < 4; mf++) {
        int co = co0 + mwbase + mf * 16 + gid;
        float* base0 = g_qkv + (((size_t)b * C3 + co) * HH + h) * WW;
        float* base1 = g_qkv + (((size_t)b * C3 + co + 8) * HH + h) * WW;
#pragma unroll
        for (int nf = 0; nf < 4; nf++) {
            int w = nwbase + nf * 8 + tg * 2;
            *reinterpret_cast<float2*>(base0 + w) = make_float2(acc[mf][nf][0], acc[mf][nf][1]);
            *reinterpret_cast<float2*>(base1 + w) = make_float2(acc[mf][nf][2], acc[mf][nf][3]);
        }
    }
}

// ---------------- fused attention per (b,c) slice, fp16 mma ----------------
// smem: qhat[128][128]h, khat[128][128]h, v[128][128]h  (256B rows, swizzled)
// Warp wp owns output rows m0=wp*16..+15. S = qhat @ khat^T (norms folded in),
// softmax in regs (C-frag -> A-frag repack), O = P @ V via ldmatrix.trans.
__global__ __launch_bounds__(256, 1) void attn_mma(const float* __restrict__ scale)
{
    extern __shared__ __align__(1024) char smem[];
    const uint32_t sb = smem_to_u32(smem);
    const uint32_t QS = 0, KS = 32768, VS = 65536;
    const int bc = blockIdx.x, b = bc >> 7, c = bc & 127;
    const int tid = threadIdx.x, lane = tid & 31, wp = tid >> 5;
    const unsigned FULL = 0xffffffffu;

    const float* qg = g_qkv + ((size_t)b * C3 + c) * HW;
    const float* kg = g_qkv + ((size_t)b * C3 + CH + c) * HW;
    const float* vg = g_qkv + ((size_t)b * C3 + 2 * CH + c) * HW;

    // stage + normalize (warp per row, 16 rows each of q,k,v)
    const int su = lane >> 1;            // 16B unit index (0..15)
    const int so = (lane & 1) * 8;       // byte offset inside unit
#pragma unroll 1
    for (int j = 0; j < 16; j++) {
        int row = wp * 16 + j;
        uint32_t dswz = (uint32_t)(row * 256 + ((su ^ (row & 7)) << 4) + so);
        // q
        float4 qv = *reinterpret_cast<const float4*>(qg + (size_t)row * 128 + lane * 4);
        float ss = qv.x * qv.x + qv.y * qv.y + qv.z * qv.z + qv.w * qv.w;
#pragma unroll
        for (int off = 16; off; off >>= 1) ss += __shfl_xor_sync(FULL, ss, off);
        float f = 1.0f / fmaxf(sqrtf(ss), 1e-12f);
        __half2 h01 = __floats2half2_rn(qv.x * f, qv.y * f);
        __half2 h23 = __floats2half2_rn(qv.z * f, qv.w * f);
        uint2 pk; pk.x = *(uint32_t*)&h01; pk.y = *(uint32_t*)&h23;
        asm volatile("st.shared.v2.b32 [%0], {%1,%2};" :: "r"(sb + QS + dswz), "r"(pk.x), "r"(pk.y));
        // k
        float4 kv = *reinterpret_cast<const float4*>(kg + (size_t)row * 128 + lane * 4);
        ss = kv.x * kv.x + kv.y * kv.y + kv.z * kv.z + kv.w * kv.w;
#pragma unroll
        for (int off = 16; off; off >>= 1) ss += __shfl_xor_sync(FULL, ss, off);
        f = 1.0f / fmaxf(sqrtf(ss), 1e-12f);
        h01 = __floats2half2_rn(kv.x * f, kv.y * f);
        h23 = __floats2half2_rn(kv.z * f, kv.w * f);
        pk.x = *(uint32_t*)&h01; pk.y = *(uint32_t*)&h23;
        asm volatile("st.shared.v2.b32 [%0], {%1,%2};" :: "r"(sb + KS + dswz), "r"(pk.x), "r"(pk.y));
        // v
        float4 vv = *reinterpret_cast<const float4*>(vg + (size_t)row * 128 + lane * 4);
        h01 = __floats2half2_rn(vv.x, vv.y);
        h23 = __floats2half2_rn(vv.z, vv.w);
        pk.x = *(uint32_t*)&h01; pk.y = *(uint32_t*)&h23;
        asm volatile("st.shared.v2.b32 [%0], {%1,%2};" :: "r"(sb + VS + dswz), "r"(pk.x), "r"(pk.y));
    }
    __syncthreads();

    const int m0 = wp * 16;
    const int q4 = lane >> 3;
    const int qr = (q4 & 1) * 8 + (lane & 7);
    const int qk = q4 >> 1;

    // S = qhat @ khat^T  (16 x 128 per warp)
    float sacc[16][4];
#pragma unroll
    for (int nt = 0; nt < 16; nt++)
#pragma unroll
        for (int k = 0; k < 4; k++) sacc[nt][k] = 0.f;

#pragma unroll 1
    for (int ks = 0; ks < 8; ks++) {
        const int u = ks * 2 + qk;
        uint32_t a[4];
        int ar = m0 + qr;
        LDSM_X4(a[0], a[1], a[2], a[3],
                sb + QS + (uint32_t)(ar * 256 + ((u ^ (ar & 7)) << 4)));
#pragma unroll
        for (int nt2 = 0; nt2 < 8; nt2++) {
            uint32_t bb[4];
            int br = nt2 * 16 + qr;
            LDSM_X4(bb[0], bb[1], bb[2], bb[3],
                    sb + KS + (uint32_t)(br * 256 + ((u ^ (br & 7)) << 4)));
            MMA16816(sacc[2 * nt2],     a, bb[0], bb[2]);
            MMA16816(sacc[2 * nt2 + 1], a, bb[1], bb[3]);
        }
    }

    // softmax (rows r0 = m0 + lane>>2 and r0+8)
    const float sc = __ldg(scale + c);
    float mx0 = -1e30f, mx1 = -1e30f;
#pragma unroll
    for (int nt = 0; nt < 16; nt++) {
        sacc[nt][0] *= sc; sacc[nt][1] *= sc; sacc[nt][2] *= sc; sacc[nt][3] *= sc;
        mx0 = fmaxf(mx0, fmaxf(sacc[nt][0], sacc[nt][1]));
        mx1 = fmaxf(mx1, fmaxf(sacc[nt][2], sacc[nt][3]));
    }
    mx0 = fmaxf(mx0, __shfl_xor_sync(FULL, mx0, 1));
    mx0 = fmaxf(mx0, __shfl_xor_sync(FULL, mx0, 2));
    mx1 = fmaxf(mx1, __shfl_xor_sync(FULL, mx1, 1));
    mx1 = fmaxf(mx1, __shfl_xor_sync(FULL, mx1, 2));
    float sum0 = 0.f, sum1 = 0.f;
#pragma unroll
    for (int nt = 0; nt < 16; nt++) {
        sacc[nt][0] = __expf(sacc[nt][0] - mx0);
        sacc[nt][1] = __expf(sacc[nt][1] - mx0);
        sacc[nt][2] = __expf(sacc[nt][2] - mx1);
        sacc[nt][3] = __expf(sacc[nt][3] - mx1);
        sum0 += sacc[nt][0] + sacc[nt][1];
        sum1 += sacc[nt][2] + sacc[nt][3];
    }
    sum0 += __shfl_xor_sync(FULL, sum0, 1); sum0 += __shfl_xor_sync(FULL, sum0, 2);
    sum1 += __shfl_xor_sync(FULL, sum1, 1); sum1 += __shfl_xor_sync(FULL, sum1, 2);
    const float inv0 = 1.0f / sum0, inv1 = 1.0f / sum1;

    // pack P into A fragments: pf[ks] covers g in [16ks, 16ks+16)
    uint32_t pf[8][4];
#pragma unroll
    for (int ks = 0; ks < 8; ks++) {
        __half2 t;
        t = __floats2half2_rn(sacc[2 * ks][0],     sacc[2 * ks][1]);     pf[ks][0] = *(uint32_t*)&t;
        t = __floats2half2_rn(sacc[2 * ks][2],     sacc[2 * ks][3]);     pf[ks][1] = *(uint32_t*)&t;
        t = __floats2half2_rn(sacc[2 * ks + 1][0], sacc[2 * ks + 1][1]); pf[ks][2] = *(uint32_t*)&t;
        t = __floats2half2_rn(sacc[2 * ks + 1][2], sacc[2 * ks + 1][3]); pf[ks][3] = *(uint32_t*)&t;
    }

    // O = P @ V
    float oacc[16][4];
#pragma unroll
    for (int nt = 0; nt < 16; nt++)
#pragma unroll
        for (int k = 0; k < 4; k++) oacc[nt][k] = 0.f;

#pragma unroll 1
    for (int ks = 0; ks < 8; ks++) {
        const int g0 = ks * 16;
        const int vrow = g0 + (lane & 15);
#pragma unroll
        for (int ntw = 0; ntw < 8; ntw++) {
            const int wu = ntw * 2 + (lane >> 4);
            uint32_t vv0, vv1, vv2, vv3;
            LDSM_X4_T(vv0, vv1, vv2, vv3,
                      sb + VS + (uint32_t)(vrow * 256 + ((wu ^ (vrow & 7)) << 4)));
            MMA16816(oacc[2 * ntw],     pf[ks], vv0, vv1);
            MMA16816(oacc[2 * ntw + 1], pf[ks], vv2, vv3);
        }
    }

    // epilogue
    const int r0 = m0 + (lane >> 2), wq = 2 * (lane & 3);
    float* ob0 = g_att + (((size_t)b * CH + c) * HH + r0) * WW;
    float* ob1 = g_att + (((size_t)b * CH + c) * HH + r0 + 8) * WW;
#pragma unroll
    for (int nt = 0; nt < 16; nt++) {
        int w = nt * 8 + wq;
        *reinterpret_cast<float2*>(ob0 + w) = make_float2(oacc[nt][0] * inv0, oacc[nt][1] * inv0);
        *reinterpret_cast<float2*>(ob1 + w) = make_float2(oacc[nt][2] * inv1, oacc[nt][3] * inv1);
    }
}

// ---------------- proj 1x1 fp32 (NCHW) ----------------
__global__ __launch_bounds__(256) void gemm1x1_kernel(
    const float* __restrict__ X, const float* __restrict__ Wt,
    float* __restrict__ Y, int M)
{
    extern __shared__ float smf[];
    float* Xs = smf;
    float* Ws = smf + 128 * 128;
    const int row = blockIdx.x, b = row >> 7, hrow = row & 127;
    const int co0 = blockIdx.y * 64, tid = threadIdx.x;
    {
        const float* xb = X + ((size_t)b * CH) * HW + (size_t)hrow * WW;
        for (int i4 = tid; i4 < 128 * 32; i4 += 256) {
            int ci = i4 >> 5, w4 = (i4 & 31) << 2;
            *reinterpret_cast<float4*>(Xs + ci * 128 + w4) =
                *reinterpret_cast<const float4*>(xb + (size_t)ci * HW + w4);
        }
    }
    for (int idx = tid; idx < 64 * 128; idx += 256) {
        int co = idx >> 7, ci = idx & 127;
        Ws[ci * 68 + co] = Wt[(size_t)(co0 + co) * 128 + ci];
    }
    __syncthreads();
    const int tx = tid & 31, ty = tid >> 5, w0 = tx * 4, c0 = ty * 8;
    float acc[8][4];
#pragma unroll
    for (int j = 0; j < 8; j++)
#pragma unroll
        for (int m = 0; m < 4; m++) acc[j][m] = 0.f;
#pragma unroll 2
    for (int ci = 0; ci < 128; ci++) {
        float4 xv = *reinterpret_cast<const float4*>(Xs + ci * 128 + w0);
        const float* wr = Ws + ci * 68 + c0;
        float4 wa = *reinterpret_cast<const float4*>(wr);
        float4 wb = *reinterpret_cast<const float4*>(wr + 4);
        float wv[8] = {wa.x, wa.y, wa.z, wa.w, wb.x, wb.y, wb.z, wb.w};
#pragma unroll
        for (int j = 0; j < 8; j++) {
            acc[j][0] += wv[j] * xv.x; acc[j][1] += wv[j] * xv.y;
            acc[j][2] += wv[j] * xv.z; acc[j][3] += wv[j] * xv.w;
        }
    }
#pragma unroll
    for (int j = 0; j < 8; j++) {
        float4 o = make_float4(acc[j][0], acc[j][1], acc[j][2], acc[j][3]);
        *reinterpret_cast<float4*>(
            Y + (((size_t)b * M + co0 + c0 + j) * HH + hrow) * WW + w0) = o;
    }
}

// ---------------- launch ----------------
extern "C" void kernel_launch(void* const* d_in, const int* in_sizes, int n_in,
                              void* d_out, int out_size)
{
    (void)in_sizes; (void)n_in; (void)out_size;
    const float* x     = (const float*)d_in[0];
    const float* w1    = (const float*)d_in[1];
    const float* w2    = (const float*)d_in[2];
    const float* wproj = (const float*)d_in[3];
    const float* scale = (const float*)d_in[4];
    float* out = (float*)d_out;

    void* p_att = nullptr;
    cudaGetSymbolAddress(&p_att, g_att);

    const int SMEM_GEMM = (128 * 128 + 128 * 68) * 4;   // 100,352 B
    const int SMEM_CONV = 2 * 32768;                    //  65,536 B
    const int SMEM_ATTN = 3 * 32768;                    //  98,304 B

    cudaFuncSetAttribute(gemm1x1_qkv,    cudaFuncAttributeMaxDynamicSharedMemorySize, SMEM_GEMM);
    cudaFuncSetAttribute(gemm1x1_kernel, cudaFuncAttributeMaxDynamicSharedMemorySize, SMEM_GEMM);
    cudaFuncSetAttribute(conv3x3_mma,    cudaFuncAttributeMaxDynamicSharedMemorySize, SMEM_CONV);
    cudaFuncSetAttribute(attn_mma,       cudaFuncAttributeMaxDynamicSharedMemorySize, SMEM_ATTN);

    wprep_kernel<<<(384 * 384 * 9 + 255) / 256, 256>>>(w2);
    gemm1x1_qkv<<<dim3(BDIM * HH, C3 / 64), 256, SMEM_GEMM>>>(x, w1);
    conv3x3_mma<<<dim3(BDIM * HH, C3 / 128), 256, SMEM_CONV>>>();
    attn_mma<<<BDIM * CH, 256, SMEM_ATTN>>>(scale);
    gemm1x1_kernel<<<dim3(BDIM * HH, CH / 64), 256, SMEM_GEMM>>>(
        (const float*)p_att, wproj, out, CH);
}

// round 6
// speedup vs baseline: 16.0911x; 2.0371x over previous
#include <cuda_runtime.h>
#include <cuda_fp16.h>
#include <cstdint>
#include <math.h>

#define BDIM 4
#define CH   128
#define C3   384
#define HH   128
#define WW   128
#define HW   (HH*WW)

__device__ __half g_x [(size_t)BDIM * HH * WW * CH];   // x in NHWC fp16 (128 ch)
__device__ __half g_wp[3 * 384 * 384];                 // Weff [r][co][s*128+ci] fp16
__device__ float g_qkv[(size_t)BDIM * C3 * HW];        // conv3x3 out NCHW fp32
__device__ float g_att[(size_t)BDIM * CH * HW];

__device__ __forceinline__ uint32_t smem_to_u32(const void* p) {
    uint32_t a;
    asm("{ .reg .u64 t; cvta.to.shared.u64 t, %1; cvt.u32.u64 %0, t; }" : "=r"(a) : "l"(p));
    return a;
}
#define CP_ASYNC16(dst, src, sz) \
    asm volatile("cp.async.cg.shared.global [%0], [%1], 16, %2;" \
        :: "r"(dst), "l"(src), "r"(sz) : "memory")
#define CP_COMMIT() asm volatile("cp.async.commit_group;" ::: "memory")
#define CP_WAIT(n)  asm volatile("cp.async.wait_group %0;" :: "n"(n) : "memory")

#define LDSM_X4(r0, r1, r2, r3, addr) \
    asm volatile("ldmatrix.sync.aligned.m8n8.x4.shared.b16 {%0,%1,%2,%3}, [%4];" \
        : "=r"(r0), "=r"(r1), "=r"(r2), "=r"(r3) : "r"(addr))
#define LDSM_X4_T(r0, r1, r2, r3, addr) \
    asm volatile("ldmatrix.sync.aligned.m8n8.x4.trans.shared.b16 {%0,%1,%2,%3}, [%4];" \
        : "=r"(r0), "=r"(r1), "=r"(r2), "=r"(r3) : "r"(addr))

#define MMA16816(c, a, b0v, b1v) \
    asm volatile("mma.sync.aligned.m16n8k16.row.col.f32.f16.f16.f32 " \
        "{%0,%1,%2,%3}, {%4,%5,%6,%7}, {%8,%9}, {%0,%1,%2,%3};" \
        : "+f"((c)[0]), "+f"((c)[1]), "+f"((c)[2]), "+f"((c)[3]) \
        : "r"((a)[0]), "r"((a)[1]), "r"((a)[2]), "r"((a)[3]), "r"(b0v), "r"(b1v))

// ---------------- xprep: x NCHW fp32 -> NHWC fp16 (CTA per (b,h) row) --------
__global__ __launch_bounds__(256) void xprep_kernel(const float* __restrict__ X)
{
    extern __shared__ float smf[];              // Xs[128ci][132]
    const int row = blockIdx.x, b = row >> 7, h = row & 127;
    const int tid = threadIdx.x;
    const float* xb = X + ((size_t)b * CH) * HW + (size_t)h * WW;
    for (int i4 = tid; i4 < 128 * 32; i4 += 256) {
        int ci = i4 >> 5, w4 = (i4 & 31) << 2;
        *reinterpret_cast<float4*>(smf + ci * 132 + w4) =
            *reinterpret_cast<const float4*>(xb + (size_t)ci * HW + w4);
    }
    __syncthreads();
#pragma unroll
    for (int j = 0; j < 8; j++) {
        int unit = tid + j * 256;               // 0..2047
        int w = unit >> 4, ci0 = (unit & 15) * 8;
        __half hb[8];
#pragma unroll
        for (int k = 0; k < 8; k++) hb[k] = __float2half(smf[(ci0 + k) * 132 + w]);
        *reinterpret_cast<uint4*>(g_x + ((size_t)(b * 128 + h) * 128 + w) * 128 + ci0) =
            *reinterpret_cast<uint4*>(hb);
    }
}

// ---------------- weff: Weff[co,ci;r,s] = sum_c W2[co,c,r,s] W1[c,ci] --------
// grid (9 rs, 6 co-blocks of 64). K=384 in chunks of 64.
__global__ __launch_bounds__(256) void weff_kernel(
    const float* __restrict__ W2, const float* __restrict__ W1)
{
    extern __shared__ float smf[];
    float* W1s = smf;                 // [64c][128ci]
    float* W2s = smf + 64 * 128;      // [64c][68]
    const int rs = blockIdx.x, r = rs / 3, s = rs % 3;
    const int co0 = blockIdx.y * 64;
    const int tid = threadIdx.x;
    const int tx = tid & 31, ty = tid >> 5;     // ci grp (x4), co grp (x8)

    float acc[8][4];
#pragma unroll
    for (int j = 0; j < 8; j++)
#pragma unroll
        for (int m = 0; m < 4; m++) acc[j][m] = 0.f;

    for (int c0 = 0; c0 < 384; c0 += 64) {
        __syncthreads();
        for (int i4 = tid; i4 < 64 * 32; i4 += 256) {
            int c = i4 >> 5, ci4 = (i4 & 31) << 2;
            *reinterpret_cast<float4*>(W1s + c * 128 + ci4) =
                *reinterpret_cast<const float4*>(W1 + (size_t)(c0 + c) * 128 + ci4);
        }
        for (int idx = tid; idx < 4096; idx += 256) {
            int co = idx & 63, c = idx >> 6;
            W2s[c * 68 + co] = W2[(size_t)(co0 + co) * 3456 + (c0 + c) * 9 + r * 3 + s];
        }
        __syncthreads();
#pragma unroll 2
        for (int c = 0; c < 64; c++) {
            float4 xv = *reinterpret_cast<const float4*>(W1s + c * 128 + tx * 4);
            const float* wr = W2s + c * 68 + ty * 8;
            float4 wa = *reinterpret_cast<const float4*>(wr);
            float4 wb = *reinterpret_cast<const float4*>(wr + 4);
            float wv[8] = {wa.x, wa.y, wa.z, wa.w, wb.x, wb.y, wb.z, wb.w};
#pragma unroll
            for (int j = 0; j < 8; j++) {
                acc[j][0] += wv[j] * xv.x; acc[j][1] += wv[j] * xv.y;
                acc[j][2] += wv[j] * xv.z; acc[j][3] += wv[j] * xv.w;
            }
        }
    }
#pragma unroll
    for (int j = 0; j < 8; j++) {
        __half hb[4];
#pragma unroll
        for (int m = 0; m < 4; m++) hb[m] = __float2half(acc[j][m]);
        int co = co0 + ty * 8 + j;
        *reinterpret_cast<uint2*>(g_wp + (size_t)(r * 384 + co) * 384 + s * 128 + tx * 4) =
            *reinterpret_cast<uint2*>(hb);
    }
}

// ---------------- conv3x3 via mma.sync fp16, K = 3r x 384 (s,ci fused) ------
// CTA: 128 couts x 128 pixels (one image row). 8 warps = 2(m) x 4(n).
#define NCHUNK 18
__global__ __launch_bounds__(256, 2) void conv3x3_mma()
{
    extern __shared__ __align__(1024) char smem[];
    const uint32_t sb = smem_to_u32(smem);
    const int tid = threadIdx.x, wid = tid >> 5, lane = tid & 31;
    const int bx = blockIdx.x, b = bx >> 7, h = bx & 127;
    const int co0 = blockIdx.y * 128;
    const int wm = wid & 1, wn = wid >> 1;
    const int mwbase = wm * 64, nwbase = wn * 32;

    float acc[4][4][4];
#pragma unroll
    for (int i = 0; i < 4; i++)
#pragma unroll
        for (int j = 0; j < 4; j++)
#pragma unroll
            for (int k = 0; k < 4; k++) acc[i][j][k] = 0.f;

    auto stage = [&](int it, int buf) {
        const int r = it / 6, kc = it % 6;
        const uint32_t abase = sb + (uint32_t)buf * 32768u;
        const uint32_t bbase = abase + 16384u;
#pragma unroll
        for (int j = 0; j < 8; j++) {
            int idx = tid + j * 256;            // 0..2047
            int rw  = (idx >> 3) & 127;
            int u   = idx & 7;
            uint32_t dof = (uint32_t)(rw * 128 + ((u ^ (rw & 7)) << 4));
            if (idx < 1024) {
                const __half* src = g_wp +
                    ((size_t)(r * 384 + co0 + rw) * 384 + kc * 64 + u * 8);
                CP_ASYNC16(abase + dof, src, 16);
            } else {
                int hr = h + r - 1;
                int L  = (rw - 1) * 128 + kc * 64 + u * 8;
                bool ok = ((unsigned)hr < 128u) && ((unsigned)L < 16384u);
                const __half* src = g_x +
                    (ok ? ((size_t)(b * 128 + hr) * 16384 + L) : 0);
                CP_ASYNC16(bbase + dof, src, ok ? 16 : 0);
            }
        }
        CP_COMMIT();
    };

    stage(0, 0);
    for (int it = 0; it < NCHUNK; it++) {
        const int buf = it & 1;
        if (it + 1 < NCHUNK) { stage(it + 1, buf ^ 1); CP_WAIT(1); }
        else                 { CP_WAIT(0); }
        __syncthreads();

        const uint32_t abase = sb + (uint32_t)buf * 32768u;
        const uint32_t bbase = abase + 16384u;
        const int q4 = lane >> 3;
        const int qr = (q4 & 1) * 8 + (lane & 7);
        const int qk = q4 >> 1;
#pragma unroll
        for (int ks = 0; ks < 4; ks++) {
            const int u = ks * 2 + qk;
            uint32_t ah[4][4], bh[2][4];
#pragma unroll
            for (int mf = 0; mf < 4; mf++) {
                int rw = mwbase + mf * 16 + qr;
                LDSM_X4(ah[mf][0], ah[mf][1], ah[mf][2], ah[mf][3],
                        abase + (uint32_t)(rw * 128 + ((u ^ (rw & 7)) << 4)));
            }
#pragma unroll
            for (int g = 0; g < 2; g++) {
                int rw = nwbase + g * 16 + qr;
                LDSM_X4(bh[g][0], bh[g][1], bh[g][2], bh[g][3],
                        bbase + (uint32_t)(rw * 128 + ((u ^ (rw & 7)) << 4)));
            }
#pragma unroll
            for (int mf = 0; mf < 4; mf++)
#pragma unroll
                for (int nf = 0; nf < 4; nf++)
                    MMA16816(acc[mf][nf], ah[mf],
                             bh[nf >> 1][nf & 1], bh[nf >> 1][(nf & 1) + 2]);
        }
        __syncthreads();
    }

    const int gid = lane >> 2, tg = lane & 3;
#pragma unroll
    for (int mf = 0; mf < 4; mf++) {
        int co = co0 + mwbase + mf * 16 + gid;
        float* base0 = g_qkv + (((size_t)b * C3 + co) * HH + h) * WW;
        float* base1 = g_qkv + (((size_t)b * C3 + co + 8) * HH + h) * WW;
#pragma unroll
        for (int nf = 0; nf < 4; nf++) {
            int w = nwbase + nf * 8 + tg * 2;
            *reinterpret_cast<float2*>(base0 + w) = make_float2(acc[mf][nf][0], acc[mf][nf][1]);
            *reinterpret_cast<float2*>(base1 + w) = make_float2(acc[mf][nf][2], acc[mf][nf][3]);
        }
    }
}

// ---------------- fused attention per (b,c) slice, fp16 mma ----------------
__global__ __launch_bounds__(256, 1) void attn_mma(const float* __restrict__ scale)
{
    extern __shared__ __align__(1024) char smem[];
    const uint32_t sb = smem_to_u32(smem);
    const uint32_t QS = 0, KS = 32768, VS = 65536;
    const int bc = blockIdx.x, b = bc >> 7, c = bc & 127;
    const int tid = threadIdx.x, lane = tid & 31, wp = tid >> 5;
    const unsigned FULL = 0xffffffffu;

    const float* qg = g_qkv + ((size_t)b * C3 + c) * HW;
    const float* kg = g_qkv + ((size_t)b * C3 + CH + c) * HW;
    const float* vg = g_qkv + ((size_t)b * C3 + 2 * CH + c) * HW;

    const int su = lane >> 1;
    const int so = (lane & 1) * 8;
#pragma unroll 1
    for (int j = 0; j < 16; j++) {
        int row = wp * 16 + j;
        uint32_t dswz = (uint32_t)(row * 256 + ((su ^ (row & 7)) << 4) + so);
        float4 qv = *reinterpret_cast<const float4*>(qg + (size_t)row * 128 + lane * 4);
        float ss = qv.x * qv.x + qv.y * qv.y + qv.z * qv.z + qv.w * qv.w;
#pragma unroll
        for (int off = 16; off; off >>= 1) ss += __shfl_xor_sync(FULL, ss, off);
        float f = 1.0f / fmaxf(sqrtf(ss), 1e-12f);
        __half2 h01 = __floats2half2_rn(qv.x * f, qv.y * f);
        __half2 h23 = __floats2half2_rn(qv.z * f, qv.w * f);
        uint2 pk; pk.x = *(uint32_t*)&h01; pk.y = *(uint32_t*)&h23;
        asm volatile("st.shared.v2.b32 [%0], {%1,%2};" :: "r"(sb + QS + dswz), "r"(pk.x), "r"(pk.y));
        float4 kv = *reinterpret_cast<const float4*>(kg + (size_t)row * 128 + lane * 4);
        ss = kv.x * kv.x + kv.y * kv.y + kv.z * kv.z + kv.w * kv.w;
#pragma unroll
        for (int off = 16; off; off >>= 1) ss += __shfl_xor_sync(FULL, ss, off);
        f = 1.0f / fmaxf(sqrtf(ss), 1e-12f);
        h01 = __floats2half2_rn(kv.x * f, kv.y * f);
        h23 = __floats2half2_rn(kv.z * f, kv.w * f);
        pk.x = *(uint32_t*)&h01; pk.y = *(uint32_t*)&h23;
        asm volatile("st.shared.v2.b32 [%0], {%1,%2};" :: "r"(sb + KS + dswz), "r"(pk.x), "r"(pk.y));
        float4 vv = *reinterpret_cast<const float4*>(vg + (size_t)row * 128 + lane * 4);
        h01 = __floats2half2_rn(vv.x, vv.y);
        h23 = __floats2half2_rn(vv.z, vv.w);
        pk.x = *(uint32_t*)&h01; pk.y = *(uint32_t*)&h23;
        asm volatile("st.shared.v2.b32 [%0], {%1,%2};" :: "r"(sb + VS + dswz), "r"(pk.x), "r"(pk.y));
    }
    __syncthreads();

    const int m0 = wp * 16;
    const int q4 = lane >> 3;
    const int qr = (q4 & 1) * 8 + (lane & 7);
    const int qk = q4 >> 1;

    float sacc[16][4];
#pragma unroll
    for (int nt = 0; nt < 16; nt++)
#pragma unroll
        for (int k = 0; k < 4; k++) sacc[nt][k] = 0.f;

#pragma unroll 1
    for (int ks = 0; ks < 8; ks++) {
        const int u = ks * 2 + qk;
        uint32_t a[4];
        int ar = m0 + qr;
        LDSM_X4(a[0], a[1], a[2], a[3],
                sb + QS + (uint32_t)(ar * 256 + ((u ^ (ar & 7)) << 4)));
#pragma unroll
        for (int nt2 = 0; nt2 < 8; nt2++) {
            uint32_t bb[4];
            int br = nt2 * 16 + qr;
            LDSM_X4(bb[0], bb[1], bb[2], bb[3],
                    sb + KS + (uint32_t)(br * 256 + ((u ^ (br & 7)) << 4)));
            MMA16816(sacc[2 * nt2],     a, bb[0], bb[2]);
            MMA16816(sacc[2 * nt2 + 1], a, bb[1], bb[3]);
        }
    }

    const float sc = __ldg(scale + c);
    float mx0 = -1e30f, mx1 = -1e30f;
#pragma unroll
    for (int nt = 0; nt < 16; nt++) {
        sacc[nt][0] *= sc; sacc[nt][1] *= sc; sacc[nt][2] *= sc; sacc[nt][3] *= sc;
        mx0 = fmaxf(mx0, fmaxf(sacc[nt][0], sacc[nt][1]));
        mx1 = fmaxf(mx1, fmaxf(sacc[nt][2], sacc[nt][3]));
    }
    mx0 = fmaxf(mx0, __shfl_xor_sync(FULL, mx0, 1));
    mx0 = fmaxf(mx0, __shfl_xor_sync(FULL, mx0, 2));
    mx1 = fmaxf(mx1, __shfl_xor_sync(FULL, mx1, 1));
    mx1 = fmaxf(mx1, __shfl_xor_sync(FULL, mx1, 2));
    float sum0 = 0.f, sum1 = 0.f;
#pragma unroll
    for (int nt = 0; nt < 16; nt++) {
        sacc[nt][0] = __expf(sacc[nt][0] - mx0);
        sacc[nt][1] = __expf(sacc[nt][1] - mx0);
        sacc[nt][2] = __expf(sacc[nt][2] - mx1);
        sacc[nt][3] = __expf(sacc[nt][3] - mx1);
        sum0 += sacc[nt][0] + sacc[nt][1];
        sum1 += sacc[nt][2] + sacc[nt][3];
    }
    sum0 += __shfl_xor_sync(FULL, sum0, 1); sum0 += __shfl_xor_sync(FULL, sum0, 2);
    sum1 += __shfl_xor_sync(FULL, sum1, 1); sum1 += __shfl_xor_sync(FULL, sum1, 2);
    const float inv0 = 1.0f / sum0, inv1 = 1.0f / sum1;

    uint32_t pf[8][4];
#pragma unroll
    for (int ks = 0; ks < 8; ks++) {
        __half2 t;
        t = __floats2half2_rn(sacc[2 * ks][0],     sacc[2 * ks][1]);     pf[ks][0] = *(uint32_t*)&t;
        t = __floats2half2_rn(sacc[2 * ks][2],     sacc[2 * ks][3]);     pf[ks][1] = *(uint32_t*)&t;
        t = __floats2half2_rn(sacc[2 * ks + 1][0], sacc[2 * ks + 1][1]); pf[ks][2] = *(uint32_t*)&t;
        t = __floats2half2_rn(sacc[2 * ks + 1][2], sacc[2 * ks + 1][3]); pf[ks][3] = *(uint32_t*)&t;
    }

    float oacc[16][4];
#pragma unroll
    for (int nt = 0; nt < 16; nt++)
#pragma unroll
        for (int k = 0; k < 4; k++) oacc[nt][k] = 0.f;

#pragma unroll 1
    for (int ks = 0; ks < 8; ks++) {
        const int vrow = ks * 16 + (lane & 15);
#pragma unroll
        for (int ntw = 0; ntw < 8; ntw++) {
            const int wu = ntw * 2 + (lane >> 4);
            uint32_t vv0, vv1, vv2, vv3;
            LDSM_X4_T(vv0, vv1, vv2, vv3,
                      sb + VS + (uint32_t)(vrow * 256 + ((wu ^ (vrow & 7)) << 4)));
            MMA16816(oacc[2 * ntw],     pf[ks], vv0, vv1);
            MMA16816(oacc[2 * ntw + 1], pf[ks], vv2, vv3);
        }
    }

    const int r0 = m0 + (lane >> 2), wq = 2 * (lane & 3);
    float* ob0 = g_att + (((size_t)b * CH + c) * HH + r0) * WW;
    float* ob1 = g_att + (((size_t)b * CH + c) * HH + r0 + 8) * WW;
#pragma unroll
    for (int nt = 0; nt < 16; nt++) {
        int w = nt * 8 + wq;
        *reinterpret_cast<float2*>(ob0 + w) = make_float2(oacc[nt][0] * inv0, oacc[nt][1] * inv0);
        *reinterpret_cast<float2*>(ob1 + w) = make_float2(oacc[nt][2] * inv1, oacc[nt][3] * inv1);
    }
}

// ---------------- proj 1x1: 128co x 64pix per CTA, fp32 SIMT ----------------
__global__ __launch_bounds__(256) void proj_kernel(
    const float* __restrict__ Wt, float* __restrict__ Y)
{
    extern __shared__ float smf[];
    float* Xs = smf;                  // [128ci][68]
    float* Ws = smf + 128 * 68;       // [128ci][132]
    const int bx = blockIdx.x;
    const int row = bx >> 1, half = bx & 1;
    const int b = row >> 7, h = row & 127, wb = half * 64;
    const int tid = threadIdx.x;
    const int tx = tid & 15, ty = tid >> 4;    // pix grp (x4), co grp (x8)

    for (int i4 = tid; i4 < 128 * 16; i4 += 256) {
        int ci = i4 >> 4, w4 = (i4 & 15) << 2;
        *reinterpret_cast<float4*>(Xs + ci * 68 + w4) =
            *reinterpret_cast<const float4*>(
                g_att + (((size_t)b * CH + ci) * HH + h) * WW + wb + w4);
    }
    for (int idx = tid; idx < 128 * 128; idx += 256) {
        int co = idx >> 7, ci = idx & 127;
        Ws[ci * 132 + co] = Wt[(size_t)co * 128 + ci];
    }
    __syncthreads();

    const int w0 = tx * 4, c0 = ty * 8;
    float acc[8][4];
#pragma unroll
    for (int j = 0; j < 8; j++)
#pragma unroll
        for (int m = 0; m < 4; m++) acc[j][m] = 0.f;
#pragma unroll 2
    for (int ci = 0; ci < 128; ci++) {
        float4 xv = *reinterpret_cast<const float4*>(Xs + ci * 68 + w0);
        const float* wr = Ws + ci * 132 + c0;
        float4 wa = *reinterpret_cast<const float4*>(wr);
        float4 wb4 = *reinterpret_cast<const float4*>(wr + 4);
        float wv[8] = {wa.x, wa.y, wa.z, wa.w, wb4.x, wb4.y, wb4.z, wb4.w};
#pragma unroll
        for (int j = 0; j < 8; j++) {
            acc[j][0] += wv[j] * xv.x; acc[j][1] += wv[j] * xv.y;
            acc[j][2] += wv[j] * xv.z; acc[j][3] += wv[j] * xv.w;
        }
    }
#pragma unroll
    for (int j = 0; j < 8; j++) {
        *reinterpret_cast<float4*>(
            Y + (((size_t)b * CH + c0 + j) * HH + h) * WW + wb + w0) =
            make_float4(acc[j][0], acc[j][1], acc[j][2], acc[j][3]);
    }
}

// ---------------- launch ----------------
extern "C" void kernel_launch(void* const* d_in, const int* in_sizes, int n_in,
                              void* d_out, int out_size)
{
    (void)in_sizes; (void)n_in; (void)out_size;
    const float* x     = (const float*)d_in[0];
    const float* w1    = (const float*)d_in[1];
    const float* w2    = (const float*)d_in[2];
    const float* wproj = (const float*)d_in[3];
    const float* scale = (const float*)d_in[4];
    float* out = (float*)d_out;

    const int SMEM_XPREP = 128 * 132 * 4;               //  67,584
    const int SMEM_WEFF  = (64 * 128 + 64 * 68) * 4;    //  50,176
    const int SMEM_CONV  = 2 * 32768;                   //  65,536
    const int SMEM_ATTN  = 3 * 32768;                   //  98,304
    const int SMEM_PROJ  = (128 * 68 + 128 * 132) * 4;  // 102,400

    cudaFuncSetAttribute(xprep_kernel, cudaFuncAttributeMaxDynamicSharedMemorySize, SMEM_XPREP);
    cudaFuncSetAttribute(weff_kernel,  cudaFuncAttributeMaxDynamicSharedMemorySize, SMEM_WEFF);
    cudaFuncSetAttribute(conv3x3_mma,  cudaFuncAttributeMaxDynamicSharedMemorySize, SMEM_CONV);
    cudaFuncSetAttribute(attn_mma,     cudaFuncAttributeMaxDynamicSharedMemorySize, SMEM_ATTN);
    cudaFuncSetAttribute(proj_kernel,  cudaFuncAttributeMaxDynamicSharedMemorySize, SMEM_PROJ);

    xprep_kernel<<<BDIM * HH, 256, SMEM_XPREP>>>(x);
    weff_kernel<<<dim3(9, 6), 256, SMEM_WEFF>>>(w2, w1);
    conv3x3_mma<<<dim3(BDIM * HH, C3 / 128), 256, SMEM_CONV>>>();
    attn_mma<<<BDIM * CH, 256, SMEM_ATTN>>>(scale);
    proj_kernel<<<BDIM * HH * 2, 256, SMEM_PROJ>>>(wproj, out);
}

// round 7
// speedup vs baseline: 22.0682x; 1.3715x over previous
#include <cuda_runtime.h>
#include <cuda_fp16.h>
#include <cstdint>
#include <math.h>

#define BDIM 4
#define CH   128
#define C3   384
#define HH   128
#define WW   128
#define HW   (HH*WW)

__device__ __half g_x   [(size_t)BDIM * HH * WW * CH];  // x NHWC fp16
__device__ __half g_wp  [3 * 384 * 384];                // Weff [r][co][s*128+ci] fp16
__device__ __half g_wpj [128 * 128];                    // proj W fp16 (co,ci)
__device__ __half g_qkvh[(size_t)BDIM * C3 * HW];       // conv out (b,c,h,w) fp16
__device__ __half g_att [(size_t)BDIM * CH * HW];       // attn out (b,c,h,w) fp16

__device__ __forceinline__ uint32_t smem_to_u32(const void* p) {
    uint32_t a;
    asm("{ .reg .u64 t; cvta.to.shared.u64 t, %1; cvt.u32.u64 %0, t; }" : "=r"(a) : "l"(p));
    return a;
}
#define CP_ASYNC16(dst, src, sz) \
    asm volatile("cp.async.cg.shared.global [%0], [%1], 16, %2;" \
        :: "r"(dst), "l"(src), "r"(sz) : "memory")
#define CP_COMMIT() asm volatile("cp.async.commit_group;" ::: "memory")
#define CP_WAIT(n)  asm volatile("cp.async.wait_group %0;" :: "n"(n) : "memory")

#define LDSM_X4(r0, r1, r2, r3, addr) \
    asm volatile("ldmatrix.sync.aligned.m8n8.x4.shared.b16 {%0,%1,%2,%3}, [%4];" \
        : "=r"(r0), "=r"(r1), "=r"(r2), "=r"(r3) : "r"(addr))
#define LDSM_X4_T(r0, r1, r2, r3, addr) \
    asm volatile("ldmatrix.sync.aligned.m8n8.x4.trans.shared.b16 {%0,%1,%2,%3}, [%4];" \
        : "=r"(r0), "=r"(r1), "=r"(r2), "=r"(r3) : "r"(addr))

#define MMA16816(c, a, b0v, b1v) \
    asm volatile("mma.sync.aligned.m16n8k16.row.col.f32.f16.f16.f32 " \
        "{%0,%1,%2,%3}, {%4,%5,%6,%7}, {%8,%9}, {%0,%1,%2,%3};" \
        : "+f"((c)[0]), "+f"((c)[1]), "+f"((c)[2]), "+f"((c)[3]) \
        : "r"((a)[0]), "r"((a)[1]), "r"((a)[2]), "r"((a)[3]), "r"(b0v), "r"(b1v))

// ---------------- xprep: x NCHW fp32 -> NHWC fp16 ----------------
__global__ __launch_bounds__(256) void xprep_kernel(const float* __restrict__ X)
{
    extern __shared__ float smf[];              // [128ci][132]
    const int row = blockIdx.x, b = row >> 7, h = row & 127;
    const int tid = threadIdx.x;
    const float* xb = X + ((size_t)b * CH) * HW + (size_t)h * WW;
    for (int i4 = tid; i4 < 128 * 32; i4 += 256) {
        int ci = i4 >> 5, w4 = (i4 & 31) << 2;
        *reinterpret_cast<float4*>(smf + ci * 132 + w4) =
            *reinterpret_cast<const float4*>(xb + (size_t)ci * HW + w4);
    }
    __syncthreads();
#pragma unroll
    for (int j = 0; j < 8; j++) {
        int unit = tid + j * 256;
        int w = unit >> 4, ci0 = (unit & 15) * 8;
        __half hb[8];
#pragma unroll
        for (int k = 0; k < 8; k++) hb[k] = __float2half(smf[(ci0 + k) * 132 + w]);
        *reinterpret_cast<uint4*>(g_x + ((size_t)(b * 128 + h) * 128 + w) * 128 + ci0) =
            *reinterpret_cast<uint4*>(hb);
    }
}

// ---------------- weff: Weff[co,ci;r,s] = sum_c W2[co,c,r,s] W1[c,ci] --------
__global__ __launch_bounds__(256) void weff_kernel(
    const float* __restrict__ W2, const float* __restrict__ W1)
{
    extern __shared__ float smf[];
    float* W1s = smf;                 // [64c][128ci]
    float* W2s = smf + 64 * 128;      // [64c][68]
    const int rs = blockIdx.x, r = rs / 3, s = rs % 3;
    const int co0 = blockIdx.y * 64;
    const int tid = threadIdx.x;
    const int tx = tid & 31, ty = tid >> 5;

    float acc[8][4];
#pragma unroll
    for (int j = 0; j < 8; j++)
#pragma unroll
        for (int m = 0; m < 4; m++) acc[j][m] = 0.f;

    for (int c0 = 0; c0 < 384; c0 += 64) {
        __syncthreads();
        for (int i4 = tid; i4 < 64 * 32; i4 += 256) {
            int c = i4 >> 5, ci4 = (i4 & 31) << 2;
            *reinterpret_cast<float4*>(W1s + c * 128 + ci4) =
                *reinterpret_cast<const float4*>(W1 + (size_t)(c0 + c) * 128 + ci4);
        }
        for (int idx = tid; idx < 4096; idx += 256) {
            int co = idx & 63, c = idx >> 6;
            W2s[c * 68 + co] = W2[(size_t)(co0 + co) * 3456 + (c0 + c) * 9 + r * 3 + s];
        }
        __syncthreads();
#pragma unroll 2
        for (int c = 0; c < 64; c++) {
            float4 xv = *reinterpret_cast<const float4*>(W1s + c * 128 + tx * 4);
            const float* wr = W2s + c * 68 + ty * 8;
            float4 wa = *reinterpret_cast<const float4*>(wr);
            float4 wb = *reinterpret_cast<const float4*>(wr + 4);
            float wv[8] = {wa.x, wa.y, wa.z, wa.w, wb.x, wb.y, wb.z, wb.w};
#pragma unroll
            for (int j = 0; j < 8; j++) {
                acc[j][0] += wv[j] * xv.x; acc[j][1] += wv[j] * xv.y;
                acc[j][2] += wv[j] * xv.z; acc[j][3] += wv[j] * xv.w;
            }
        }
    }
#pragma unroll
    for (int j = 0; j < 8; j++) {
        __half hb[4];
#pragma unroll
        for (int m = 0; m < 4; m++) hb[m] = __float2half(acc[j][m]);
        int co = co0 + ty * 8 + j;
        *reinterpret_cast<uint2*>(g_wp + (size_t)(r * 384 + co) * 384 + s * 128 + tx * 4) =
            *reinterpret_cast<uint2*>(hb);
    }
}

// ---------------- wpjprep: proj weights fp32 -> fp16 ----------------
__global__ void wpjprep_kernel(const float* __restrict__ W)
{
    int i = blockIdx.x * 256 + threadIdx.x;
    if (i < 16384) g_wpj[i] = __float2half(W[i]);
}

// ---------------- conv3x3 via mma.sync fp16, K = 3r x 384 ----------------
#define NCHUNK 18
__global__ __launch_bounds__(256, 2) void conv3x3_mma()
{
    extern __shared__ __align__(1024) char smem[];
    const uint32_t sb = smem_to_u32(smem);
    const int tid = threadIdx.x, wid = tid >> 5, lane = tid & 31;
    const int bx = blockIdx.x, b = bx >> 7, h = bx & 127;
    const int co0 = blockIdx.y * 128;
    const int wm = wid & 1, wn = wid >> 1;
    const int mwbase = wm * 64, nwbase = wn * 32;

    float acc[4][4][4];
#pragma unroll
    for (int i = 0; i < 4; i++)
#pragma unroll
        for (int j = 0; j < 4; j++)
#pragma unroll
            for (int k = 0; k < 4; k++) acc[i][j][k] = 0.f;

    auto stage = [&](int it, int buf) {
        const int r = it / 6, kc = it % 6;
        const uint32_t abase = sb + (uint32_t)buf * 32768u;
        const uint32_t bbase = abase + 16384u;
#pragma unroll
        for (int j = 0; j < 8; j++) {
            int idx = tid + j * 256;
            int rw  = (idx >> 3) & 127;
            int u   = idx & 7;
            uint32_t dof = (uint32_t)(rw * 128 + ((u ^ (rw & 7)) << 4));
            if (idx < 1024) {
                const __half* src = g_wp +
                    ((size_t)(r * 384 + co0 + rw) * 384 + kc * 64 + u * 8);
                CP_ASYNC16(abase + dof, src, 16);
            } else {
                int hr = h + r - 1;
                int L  = (rw - 1) * 128 + kc * 64 + u * 8;
                bool ok = ((unsigned)hr < 128u) && ((unsigned)L < 16384u);
                const __half* src = g_x +
                    (ok ? ((size_t)(b * 128 + hr) * 16384 + L) : 0);
                CP_ASYNC16(bbase + dof, src, ok ? 16 : 0);
            }
        }
        CP_COMMIT();
    };

    stage(0, 0);
    for (int it = 0; it < NCHUNK; it++) {
        const int buf = it & 1;
        if (it + 1 < NCHUNK) { stage(it + 1, buf ^ 1); CP_WAIT(1); }
        else                 { CP_WAIT(0); }
        __syncthreads();

        const uint32_t abase = sb + (uint32_t)buf * 32768u;
        const uint32_t bbase = abase + 16384u;
        const int q4 = lane >> 3;
        const int qr = (q4 & 1) * 8 + (lane & 7);
        const int qk = q4 >> 1;
#pragma unroll
        for (int ks = 0; ks < 4; ks++) {
            const int u = ks * 2 + qk;
            uint32_t ah[4][4], bh[2][4];
#pragma unroll
            for (int mf = 0; mf < 4; mf++) {
                int rw = mwbase + mf * 16 + qr;
                LDSM_X4(ah[mf][0], ah[mf][1], ah[mf][2], ah[mf][3],
                        abase + (uint32_t)(rw * 128 + ((u ^ (rw & 7)) << 4)));
            }
#pragma unroll
            for (int g = 0; g < 2; g++) {
                int rw = nwbase + g * 16 + qr;
                LDSM_X4(bh[g][0], bh[g][1], bh[g][2], bh[g][3],
                        bbase + (uint32_t)(rw * 128 + ((u ^ (rw & 7)) << 4)));
            }
#pragma unroll
            for (int mf = 0; mf < 4; mf++)
#pragma unroll
                for (int nf = 0; nf < 4; nf++)
                    MMA16816(acc[mf][nf], ah[mf],
                             bh[nf >> 1][nf & 1], bh[nf >> 1][(nf & 1) + 2]);
        }
        __syncthreads();
    }

    const int gid = lane >> 2, tg = lane & 3;
#pragma unroll
    for (int mf = 0; mf < 4; mf++) {
        int co = co0 + mwbase + mf * 16 + gid;
        __half* base0 = g_qkvh + (((size_t)b * C3 + co) * HH + h) * WW;
        __half* base1 = g_qkvh + (((size_t)b * C3 + co + 8) * HH + h) * WW;
#pragma unroll
        for (int nf = 0; nf < 4; nf++) {
            int w = nwbase + nf * 8 + tg * 2;
            *reinterpret_cast<__half2*>(base0 + w) =
                __floats2half2_rn(acc[mf][nf][0], acc[mf][nf][1]);
            *reinterpret_cast<__half2*>(base1 + w) =
                __floats2half2_rn(acc[mf][nf][2], acc[mf][nf][3]);
        }
    }
}

// ---------------- fused attention per (b,c), cp.async staged, norms folded --
__global__ __launch_bounds__(256, 2) void attn_mma(const float* __restrict__ scale)
{
    extern __shared__ __align__(1024) char smem[];
    const uint32_t sb = smem_to_u32(smem);
    const uint32_t QS = 0, KS = 32768, VS = 65536, NV = 98304;  // NV: 256 floats
    float* ninv = reinterpret_cast<float*>(smem + NV);
    const int bc = blockIdx.x, b = bc >> 7, c = bc & 127;
    const int tid = threadIdx.x, lane = tid & 31, wp = tid >> 5;
    const unsigned FULL = 0xffffffffu;

    // stage q,k,v tiles: 3 x 128 rows x 256B, swizzled, via cp.async
    const __half* srcbase = g_qkvh + ((size_t)b * C3 + c) * HW;
#pragma unroll
    for (int j = 0; j < 24; j++) {
        int idx = tid + j * 256;                // 0..6143
        int sec = idx >> 11;                    // 0=q,1=k,2=v
        int rem = idx & 2047;
        int row = rem >> 4, u = rem & 15;
        const __half* src = srcbase + ((size_t)sec * 128) * HW + (size_t)row * WW + u * 8;
        uint32_t dst = sb + (uint32_t)sec * 32768u
                     + (uint32_t)(row * 256 + ((u ^ (row & 7)) << 4));
        CP_ASYNC16(dst, src, 16);
    }
    CP_COMMIT(); CP_WAIT(0);
    __syncthreads();

    // norms from smem: tid -> (which = tid>>7: 0=q,1=k; row = tid&127)
    {
        int which = tid >> 7, row = tid & 127;
        const char* base = smem + which * 32768 + row * 256;
        float ss = 0.f;
#pragma unroll
        for (int u = 0; u < 16; u++) {
            uint4 vv = *reinterpret_cast<const uint4*>(base + ((u ^ (row & 7)) << 4));
            float2 f;
            f = __half22float2(*reinterpret_cast<__half2*>(&vv.x)); ss += f.x * f.x + f.y * f.y;
            f = __half22float2(*reinterpret_cast<__half2*>(&vv.y)); ss += f.x * f.x + f.y * f.y;
            f = __half22float2(*reinterpret_cast<__half2*>(&vv.z)); ss += f.x * f.x + f.y * f.y;
            f = __half22float2(*reinterpret_cast<__half2*>(&vv.w)); ss += f.x * f.x + f.y * f.y;
        }
        ninv[which * 128 + row] = 1.0f / fmaxf(sqrtf(ss), 1e-12f);
    }
    __syncthreads();

    const int m0 = wp * 16;
    const int q4 = lane >> 3;
    const int qr = (q4 & 1) * 8 + (lane & 7);
    const int qk = q4 >> 1;

    // S = q @ k^T (raw)
    float sacc[16][4];
#pragma unroll
    for (int nt = 0; nt < 16; nt++)
#pragma unroll
        for (int k = 0; k < 4; k++) sacc[nt][k] = 0.f;

#pragma unroll 1
    for (int ks = 0; ks < 8; ks++) {
        const int u = ks * 2 + qk;
        uint32_t a[4];
        int ar = m0 + qr;
        LDSM_X4(a[0], a[1], a[2], a[3],
                sb + QS + (uint32_t)(ar * 256 + ((u ^ (ar & 7)) << 4)));
#pragma unroll
        for (int nt2 = 0; nt2 < 8; nt2++) {
            uint32_t bb[4];
            int br = nt2 * 16 + qr;
            LDSM_X4(bb[0], bb[1], bb[2], bb[3],
                    sb + KS + (uint32_t)(br * 256 + ((u ^ (br & 7)) << 4)));
            MMA16816(sacc[2 * nt2],     a, bb[0], bb[2]);
            MMA16816(sacc[2 * nt2 + 1], a, bb[1], bb[3]);
        }
    }

    // fold norms + scale:  rows r0, r0+8 ; cols nt*8 + (lane&3)*2 + {0,1}
    const float sc = __ldg(scale + c);
    const int r0 = m0 + (lane >> 2);
    const float qs0 = ninv[r0] * sc, qs1 = ninv[r0 + 8] * sc;
    float mx0 = -1e30f, mx1 = -1e30f;
#pragma unroll
    for (int nt = 0; nt < 16; nt++) {
        int cc = nt * 8 + (lane & 3) * 2;
        float k0 = ninv[128 + cc], k1 = ninv[128 + cc + 1];
        sacc[nt][0] *= qs0 * k0; sacc[nt][1] *= qs0 * k1;
        sacc[nt][2] *= qs1 * k0; sacc[nt][3] *= qs1 * k1;
        mx0 = fmaxf(mx0, fmaxf(sacc[nt][0], sacc[nt][1]));
        mx1 = fmaxf(mx1, fmaxf(sacc[nt][2], sacc[nt][3]));
    }
    mx0 = fmaxf(mx0, __shfl_xor_sync(FULL, mx0, 1));
    mx0 = fmaxf(mx0, __shfl_xor_sync(FULL, mx0, 2));
    mx1 = fmaxf(mx1, __shfl_xor_sync(FULL, mx1, 1));
    mx1 = fmaxf(mx1, __shfl_xor_sync(FULL, mx1, 2));
    float sum0 = 0.f, sum1 = 0.f;
#pragma unroll
    for (int nt = 0; nt < 16; nt++) {
        sacc[nt][0] = __expf(sacc[nt][0] - mx0);
        sacc[nt][1] = __expf(sacc[nt][1] - mx0);
        sacc[nt][2] = __expf(sacc[nt][2] - mx1);
        sacc[nt][3] = __expf(sacc[nt][3] - mx1);
        sum0 += sacc[nt][0] + sacc[nt][1];
        sum1 += sacc[nt][2] + sacc[nt][3];
    }
    sum0 += __shfl_xor_sync(FULL, sum0, 1); sum0 += __shfl_xor_sync(FULL, sum0, 2);
    sum1 += __shfl_xor_sync(FULL, sum1, 1); sum1 += __shfl_xor_sync(FULL, sum1, 2);
    const float inv0 = 1.0f / sum0, inv1 = 1.0f / sum1;

    uint32_t pf[8][4];
#pragma unroll
    for (int ks = 0; ks < 8; ks++) {
        __half2 t;
        t = __floats2half2_rn(sacc[2 * ks][0],     sacc[2 * ks][1]);     pf[ks][0] = *(uint32_t*)&t;
        t = __floats2half2_rn(sacc[2 * ks][2],     sacc[2 * ks][3]);     pf[ks][1] = *(uint32_t*)&t;
        t = __floats2half2_rn(sacc[2 * ks + 1][0], sacc[2 * ks + 1][1]); pf[ks][2] = *(uint32_t*)&t;
        t = __floats2half2_rn(sacc[2 * ks + 1][2], sacc[2 * ks + 1][3]); pf[ks][3] = *(uint32_t*)&t;
    }

    float oacc[16][4];
#pragma unroll
    for (int nt = 0; nt < 16; nt++)
#pragma unroll
        for (int k = 0; k < 4; k++) oacc[nt][k] = 0.f;

#pragma unroll 1
    for (int ks = 0; ks < 8; ks++) {
        const int vrow = ks * 16 + (lane & 15);
#pragma unroll
        for (int ntw = 0; ntw < 8; ntw++) {
            const int wu = ntw * 2 + (lane >> 4);
            uint32_t vv0, vv1, vv2, vv3;
            LDSM_X4_T(vv0, vv1, vv2, vv3,
                      sb + VS + (uint32_t)(vrow * 256 + ((wu ^ (vrow & 7)) << 4)));
            MMA16816(oacc[2 * ntw],     pf[ks], vv0, vv1);
            MMA16816(oacc[2 * ntw + 1], pf[ks], vv2, vv3);
        }
    }

    // epilogue -> g_att fp16 (b,c,h,w)
    const int wq = 2 * (lane & 3);
    __half* ob0 = g_att + (((size_t)b * CH + c) * HH + r0) * WW;
    __half* ob1 = g_att + (((size_t)b * CH + c) * HH + r0 + 8) * WW;
#pragma unroll
    for (int nt = 0; nt < 16; nt++) {
        int w = nt * 8 + wq;
        *reinterpret_cast<__half2*>(ob0 + w) =
            __floats2half2_rn(oacc[nt][0] * inv0, oacc[nt][1] * inv0);
        *reinterpret_cast<__half2*>(ob1 + w) =
            __floats2half2_rn(oacc[nt][2] * inv1, oacc[nt][3] * inv1);
    }
}

// ---------------- proj 1x1 via fp16 mma: CTA per (b,h) row ----------------
__global__ __launch_bounds__(256, 2) void proj_mma(float* __restrict__ Y)
{
    extern __shared__ __align__(1024) char smem[];
    const uint32_t sb = smem_to_u32(smem);
    const uint32_t WS = 0, XS = 32768;
    const int bx = blockIdx.x, b = bx >> 7, h = bx & 127;
    const int tid = threadIdx.x, wid = tid >> 5, lane = tid & 31;
    const int wm = wid & 1, wn = wid >> 1;
    const int mwbase = wm * 64, nwbase = wn * 32;

    // stage W [128co][256B] + X [128c][256B]
#pragma unroll
    for (int j = 0; j < 16; j++) {
        int idx = tid + j * 256;                // 0..4095
        int sec = idx >> 11;
        int rem = idx & 2047;
        int row = rem >> 4, u = rem & 15;
        const __half* src = sec
            ? (g_att + (((size_t)b * CH + row) * HH + h) * WW + u * 8)
            : (g_wpj + (size_t)row * 128 + u * 8);
        uint32_t dst = sb + (uint32_t)sec * 32768u
                     + (uint32_t)(row * 256 + ((u ^ (row & 7)) << 4));
        CP_ASYNC16(dst, src, 16);
    }
    CP_COMMIT(); CP_WAIT(0);
    __syncthreads();

    float acc[4][4][4];
#pragma unroll
    for (int i = 0; i < 4; i++)
#pragma unroll
        for (int j = 0; j < 4; j++)
#pragma unroll
            for (int k = 0; k < 4; k++) acc[i][j][k] = 0.f;

    const int q4 = lane >> 3;
    const int qr = (q4 & 1) * 8 + (lane & 7);
    const int qk = q4 >> 1;
#pragma unroll 1
    for (int ks = 0; ks < 8; ks++) {
        const int u = ks * 2 + qk;
        uint32_t ah[4][4];
#pragma unroll
        for (int mf = 0; mf < 4; mf++) {
            int rw = mwbase + mf * 16 + qr;
            LDSM_X4(ah[mf][0], ah[mf][1], ah[mf][2], ah[mf][3],
                    sb + WS + (uint32_t)(rw * 256 + ((u ^ (rw & 7)) << 4)));
        }
        const int vrow = ks * 16 + (lane & 15);
#pragma unroll
        for (int ntw = 0; ntw < 2; ntw++) {
            const int wu = (nwbase >> 3) + ntw * 2 + (lane >> 4);
            uint32_t vv0, vv1, vv2, vv3;
            LDSM_X4_T(vv0, vv1, vv2, vv3,
                      sb + XS + (uint32_t)(vrow * 256 + ((wu ^ (vrow & 7)) << 4)));
#pragma unroll
            for (int mf = 0; mf < 4; mf++) {
                MMA16816(acc[mf][ntw * 2],     ah[mf], vv0, vv1);
                MMA16816(acc[mf][ntw * 2 + 1], ah[mf], vv2, vv3);
            }
        }
    }

    const int gid = lane >> 2, tg = lane & 3;
#pragma unroll
    for (int mf = 0; mf < 4; mf++) {
        int co = mwbase + mf * 16 + gid;
        float* o0 = Y + (((size_t)b * CH + co) * HH + h) * WW;
        float* o1 = Y + (((size_t)b * CH + co + 8) * HH + h) * WW;
#pragma unroll
        for (int nf = 0; nf < 4; nf++) {
            int w = nwbase + nf * 8 + tg * 2;
            *reinterpret_cast<float2*>(o0 + w) = make_float2(acc[mf][nf][0], acc[mf][nf][1]);
            *reinterpret_cast<float2*>(o1 + w) = make_float2(acc[mf][nf][2], acc[mf][nf][3]);
        }
    }
}

// ---------------- launch ----------------
extern "C" void kernel_launch(void* const* d_in, const int* in_sizes, int n_in,
                              void* d_out, int out_size)
{
    (void)in_sizes; (void)n_in; (void)out_size;
    const float* x     = (const float*)d_in[0];
    const float* w1    = (const float*)d_in[1];
    const float* w2    = (const float*)d_in[2];
    const float* wproj = (const float*)d_in[3];
    const float* scale = (const float*)d_in[4];
    float* out = (float*)d_out;

    const int SMEM_XPREP = 128 * 132 * 4;               //  67,584
    const int SMEM_WEFF  = (64 * 128 + 64 * 68) * 4;    //  50,176
    const int SMEM_CONV  = 2 * 32768;                   //  65,536
    const int SMEM_ATTN  = 3 * 32768 + 1024;            //  99,328
    const int SMEM_PROJ  = 2 * 32768;                   //  65,536

    cudaFuncSetAttribute(xprep_kernel, cudaFuncAttributeMaxDynamicSharedMemorySize, SMEM_XPREP);
    cudaFuncSetAttribute(weff_kernel,  cudaFuncAttributeMaxDynamicSharedMemorySize, SMEM_WEFF);
    cudaFuncSetAttribute(conv3x3_mma,  cudaFuncAttributeMaxDynamicSharedMemorySize, SMEM_CONV);
    cudaFuncSetAttribute(attn_mma,     cudaFuncAttributeMaxDynamicSharedMemorySize, SMEM_ATTN);
    cudaFuncSetAttribute(proj_mma,     cudaFuncAttributeMaxDynamicSharedMemorySize, SMEM_PROJ);

    xprep_kernel<<<BDIM * HH, 256, SMEM_XPREP>>>(x);
    weff_kernel<<<dim3(9, 6), 256, SMEM_WEFF>>>(w2, w1);
    wpjprep_kernel<<<64, 256>>>(wproj);
    conv3x3_mma<<<dim3(BDIM * HH, C3 / 128), 256, SMEM_CONV>>>();
    attn_mma<<<BDIM * CH, 256, SMEM_ATTN>>>(scale);
    proj_mma<<<BDIM * HH, 256, SMEM_PROJ>>>(out);
}